// round 6
// baseline (speedup 1.0000x reference)
#include <cuda_runtime.h>
#include <cuda_bf16.h>
#include <cstdint>
#include <cstddef>

#define BATCH 256
#define F0    40
#define KDIM  32
#define NJ    200
#define C0    1600
#define C1    8000
#define M0    8192
#define KG    16
#define M1    512
#define Z0    2      // split-K slices layer 0
#define Z1    37     // split-K slices layer 1

// ---- scratch (static __device__, per harness rules) ----
__device__ __align__(16) __nv_bfloat16 g_A0[(size_t)M0 * 2 * C0];   // [8192, 3200]  hi|lo
__device__ __align__(16) __nv_bfloat16 g_Xp[(size_t)M1 * 2 * C1];   // [512, 16000]  hi|lo
__device__ __align__(16) __nv_bfloat16 g_B0[(size_t)256 * 2 * C0];  // [256, 3200]   hi|lo
__device__ __align__(16) __nv_bfloat16 g_B1[(size_t)256 * 2 * C1];  // [256, 16000]
__device__ __align__(16) float g_P0[(size_t)Z0 * M0 * NJ];          // gemm0 partials
__device__ __align__(16) float g_P1[(size_t)Z1 * BATCH * NJ];       // gemm1 partials
__device__ __align__(16) float g_O0[(size_t)M0 * NJ];               // summed out0

// ================= helpers =================
__device__ __forceinline__ uint32_t smem_u32(const void* p) {
    uint32_t a;
    asm("{ .reg .u64 t; cvta.to.shared.u64 t, %1; cvt.u32.u64 %0, t; }" : "=r"(a) : "l"(p));
    return a;
}

__device__ __forceinline__ void ldm_x4(uint32_t* r, uint32_t addr) {
    asm volatile("ldmatrix.sync.aligned.m8n8.x4.shared.b16 {%0,%1,%2,%3}, [%4];"
        : "=r"(r[0]), "=r"(r[1]), "=r"(r[2]), "=r"(r[3]) : "r"(addr));
}

__device__ __forceinline__ void mma_bf16(float* d, const uint32_t* a, uint32_t b0, uint32_t b1) {
    asm volatile("mma.sync.aligned.m16n8k16.row.col.f32.bf16.bf16.f32 "
        "{%0,%1,%2,%3}, {%4,%5,%6,%7}, {%8,%9}, {%0,%1,%2,%3};"
        : "+f"(d[0]), "+f"(d[1]), "+f"(d[2]), "+f"(d[3])
        : "r"(a[0]), "r"(a[1]), "r"(a[2]), "r"(a[3]), "r"(b0), "r"(b1));
}

__device__ __forceinline__ void cp16(uint32_t saddr, const void* gaddr) {
    asm volatile("cp.async.cg.shared.global [%0], [%1], 16;" :: "r"(saddr), "l"(gaddr));
}
__device__ __forceinline__ void cp_commit() { asm volatile("cp.async.commit_group;" ::: "memory"); }
__device__ __forceinline__ void cp_wait1()  { asm volatile("cp.async.wait_group 1;" ::: "memory"); }

__device__ __forceinline__ void split_store(__nv_bfloat16* hi_p, __nv_bfloat16* lo_p, float v) {
    __nv_bfloat16 h = __float2bfloat16(v);
    *hi_p = h;
    *lo_p = __float2bfloat16(v - __bfloat162float(h));
}

// ================= weight prep =================
// transpose + bf16-split cw[C,200] -> Bt[256, 2C]
__global__ void bprep_kernel(const float* __restrict__ cw, __nv_bfloat16* __restrict__ Bt, int C) {
    __shared__ float t[32][33];
    int cb = blockIdx.x * 32;
    int jb = blockIdx.y * 32;
    int tx = threadIdx.x & 31, ty = threadIdx.x >> 5;
    #pragma unroll
    for (int r = 0; r < 32; r += 8) {
        int c = cb + ty + r;
        int j = jb + tx;
        t[ty + r][tx] = (j < NJ) ? cw[(size_t)c * NJ + j] : 0.f;
    }
    __syncthreads();
    #pragma unroll
    for (int r = 0; r < 32; r += 8) {
        int j = jb + ty + r;
        int c = cb + tx;
        float v = t[tx][ty + r];
        split_store(&Bt[(size_t)j * (2 * C) + c], &Bt[(size_t)j * (2 * C) + C + c], v);
    }
}

// ---------------- Layer 0 producer -> A0 bf16 hi|lo ----------------
__global__ void __launch_bounds__(128) prep0_kernel(
    const float* __restrict__ inp, const float* __restrict__ wq,
    const float* __restrict__ wk, const float* __restrict__ wv,
    __nv_bfloat16* __restrict__ A0)
{
    __shared__ float u[F0], w[F0], v[F0], Sinv[F0];
    __shared__ float E[C0];
    int bk = blockIdx.x;
    int b = bk >> 5, k = bk & 31;
    int tid = threadIdx.x;

    if (tid < F0) {
        float x = inp[(size_t)(b * F0 + tid) * KDIM + k];
        u[tid] = x * wk[tid * KDIM + k];
        w[tid] = x * wv[tid * KDIM + k];
        v[tid] = x * wq[tid * KDIM + k];
    }
    __syncthreads();
    for (int idx = tid; idx < C0; idx += 128) {
        int f = idx / 40, g = idx - f * 40;
        E[idx] = __expf(u[f] * v[g]);
    }
    __syncthreads();
    if (tid < F0) {
        float s = 0.f;
        #pragma unroll
        for (int f = 0; f < F0; f++) s += E[f * 40 + tid];
        Sinv[tid] = 1.0f / s;
    }
    __syncthreads();
    __nv_bfloat16* rowp = A0 + (size_t)bk * (2 * C0);
    for (int idx = tid; idx < C0; idx += 128) {
        int f = idx / 40, g = idx - f * 40;
        float val = w[f] * E[idx] * Sinv[g];
        split_store(&rowp[idx], &rowp[C0 + idx], val);
    }
}

// ---------------- Layer 1 producer: split-g, register-accumulated ----------------
__global__ void __launch_bounds__(256) prep1_kernel(
    const float* __restrict__ inp, const float* __restrict__ out0,
    const float* __restrict__ wq, const float* __restrict__ wk,
    const float* __restrict__ wv, __nv_bfloat16* __restrict__ Xp)
{
    __shared__ float u[F0], w[F0], vl[50], Sinv[50];
    __shared__ float E[2000];
    const int blk = blockIdx.x;       // 2048
    const int gq = blk & 3;
    const int bk2 = blk >> 2;
    const int kg = bk2 & 1;
    const int b = bk2 >> 1;
    const int tid = threadIdx.x;
    const int gbase = gq * 50;

    int fi[8], gi[8];
    bool ok[8];
    float acc[8];
    #pragma unroll
    for (int i = 0; i < 8; i++) {
        int id = tid + 256 * i;
        ok[i] = (id < 2000);
        int idc = ok[i] ? id : 0;
        fi[i] = idc / 50;
        gi[i] = idc - fi[i] * 50;
        acc[i] = 0.f;
    }

    for (int kk = 0; kk < KG; kk++) {
        int k = kg * KG + kk;
        __syncthreads();
        if (tid < F0) {
            float x = inp[(size_t)(b * F0 + tid) * KDIM + k];
            u[tid] = x * wk[tid * KDIM + k];
            w[tid] = x * wv[tid * KDIM + k];
        }
        if (tid >= 64 && tid < 114) {
            int g = tid - 64;
            vl[g] = out0[(size_t)(b * KDIM + k) * NJ + gbase + g] * wq[(gbase + g) * KDIM + k];
        }
        __syncthreads();
        float e[8];
        #pragma unroll
        for (int i = 0; i < 8; i++) {
            e[i] = __expf(u[fi[i]] * vl[gi[i]]);
            if (ok[i]) E[tid + 256 * i] = e[i];
        }
        __syncthreads();
        if (tid < 50) {
            float s = 0.f;
            #pragma unroll
            for (int f = 0; f < F0; f++) s += E[f * 50 + tid];
            Sinv[tid] = 1.0f / s;
        }
        __syncthreads();
        #pragma unroll
        for (int i = 0; i < 8; i++)
            acc[i] += w[fi[i]] * e[i] * Sinv[gi[i]];
    }

    __nv_bfloat16* rowp = Xp + (size_t)(b * 2 + kg) * (2 * C1);
    #pragma unroll
    for (int i = 0; i < 8; i++) {
        if (!ok[i]) continue;
        int c = fi[i] * NJ + gbase + gi[i];
        split_store(&rowp[c], &rowp[C1 + c], acc[i]);
    }
}

// ---------------- mma.sync bf16x3 GEMM, 128x128 tile, 3-stage cp.async ----------
// Uniform guards skip all MMA/ldmatrix/cp work on columns >= NJ (pad region).
__global__ void __launch_bounds__(256, 2) mma_gemm_kernel(
    const __nv_bfloat16* __restrict__ A,
    const __nv_bfloat16* __restrict__ B,
    float* __restrict__ P, size_t sliceStride,
    int K, int cpz, int nc, int fold)
{
    extern __shared__ char sm[];       // 3 stages x (A 16KB + B 16KB) = 96KB
    const int tid = threadIdx.x;
    const int lane = tid & 31;
    const int wid = tid >> 5;
    const int wm0 = (wid & 3) * 32;
    const int wn0 = (wid >> 2) * 64;
    const int m0 = blockIdx.x * 128;
    const int n0 = blockIdx.y * 128;
    const int nvalid = NJ - n0;        // valid cols in this n-tile (200 or 72)
    const int brows = (nvalid >= 128) ? 128 : ((nvalid + 15) & ~15);
    const int cpk = K / 64;
    const int lda = 2 * K;
    const int c0 = blockIdx.z * cpz;
    int c1 = c0 + cpz; if (c1 > nc) c1 = nc;

    const uint32_t sb = smem_u32(sm);
    float* Pz = P + (size_t)blockIdx.z * sliceStride;

    float acc[2][8][4];
    #pragma unroll
    for (int i = 0; i < 2; i++)
        #pragma unroll
        for (int j = 0; j < 8; j++)
            #pragma unroll
            for (int l = 0; l < 4; l++) acc[i][j][l] = 0.f;

    auto gissue = [&](int c, int st) {
        int region = c / cpk;
        int within = c - region * cpk;
        int acol = (region == 1 ? K : 0) + within * 64;
        int bcol = (region == 2 ? K : 0) + within * 64;
        uint32_t abase = sb + st * 32768;
        uint32_t bbase = abase + 16384;
        #pragma unroll
        for (int i = 0; i < 4; i++) {
            int idx = tid + 256 * i;
            int row = idx >> 3, q = idx & 7;
            cp16(abase + (row * 8 + (q ^ (row & 7))) * 16,
                 A + (size_t)(m0 + row) * lda + acol + q * 8);
        }
        #pragma unroll
        for (int i = 0; i < 4; i++) {
            int idx = tid + 256 * i;
            int row = idx >> 3, q = idx & 7;
            if (row < brows)
                cp16(bbase + (row * 8 + (q ^ (row & 7))) * 16,
                     B + (size_t)(n0 + row) * lda + bcol + q * 8);
        }
        cp_commit();
    };

    // prologue: 2 groups always committed
    if (c0 < c1) gissue(c0, 0); else cp_commit();
    if (c0 + 1 < c1) gissue(c0 + 1, 1); else cp_commit();

    const int t3 = lane >> 3;
    const int r8 = lane & 7;

    for (int c = c0; c < c1; c++) {
        int rel = c - c0;
        int st = rel % 3;
        cp_wait1();
        __syncthreads();
        if (c + 2 < c1) gissue(c + 2, (rel + 2) % 3);
        uint32_t ab = sb + st * 32768;
        uint32_t bb = ab + 16384;
        #pragma unroll
        for (int ks = 0; ks < 4; ks++) {
            int kc = ks * 2;
            uint32_t afr[2][4], bfr[4][4];
            #pragma unroll
            for (int mt = 0; mt < 2; mt++) {
                int m = wm0 + mt * 16 + (t3 & 1) * 8 + r8;
                int q = kc + (t3 >> 1);
                ldm_x4(afr[mt], ab + (m * 8 + (q ^ (m & 7))) * 16);
            }
            #pragma unroll
            for (int np = 0; np < 4; np++) {
                if (wn0 + np * 16 < nvalid) {          // warp-uniform guard
                    int n = wn0 + np * 16 + (t3 >> 1) * 8 + r8;
                    int q = kc + (t3 & 1);
                    ldm_x4(bfr[np], bb + (n * 8 + (q ^ (n & 7))) * 16);
                }
            }
            #pragma unroll
            for (int mt = 0; mt < 2; mt++)
                #pragma unroll
                for (int nt = 0; nt < 8; nt++)
                    if (wn0 + nt * 8 < nvalid)         // warp-uniform guard
                        mma_bf16(acc[mt][nt], afr[mt],
                                 bfr[nt >> 1][(nt & 1) * 2], bfr[nt >> 1][(nt & 1) * 2 + 1]);
        }
    }

    // epilogue: plain vectorized stores into this z-slice
    const int g = lane >> 2, t = lane & 3;
    if (!fold) {
        #pragma unroll
        for (int mt = 0; mt < 2; mt++) {
            #pragma unroll
            for (int nt = 0; nt < 8; nt++) {
                int row = m0 + wm0 + mt * 16 + g;
                int col = n0 + wn0 + nt * 8 + t * 2;
                if (col < NJ) {
                    *reinterpret_cast<float2*>(&Pz[(size_t)row * NJ + col]) =
                        make_float2(acc[mt][nt][0], acc[mt][nt][1]);
                    *reinterpret_cast<float2*>(&Pz[(size_t)(row + 8) * NJ + col]) =
                        make_float2(acc[mt][nt][2], acc[mt][nt][3]);
                }
            }
        }
    } else {
        #pragma unroll
        for (int mt = 0; mt < 2; mt++) {
            #pragma unroll
            for (int nt = 0; nt < 8; nt++) {
                float v0 = acc[mt][nt][0] + __shfl_xor_sync(0xFFFFFFFFu, acc[mt][nt][0], 4);
                float v1 = acc[mt][nt][1] + __shfl_xor_sync(0xFFFFFFFFu, acc[mt][nt][1], 4);
                float v2 = acc[mt][nt][2] + __shfl_xor_sync(0xFFFFFFFFu, acc[mt][nt][2], 4);
                float v3 = acc[mt][nt][3] + __shfl_xor_sync(0xFFFFFFFFu, acc[mt][nt][3], 4);
                int row = m0 + wm0 + mt * 16 + g;
                int col = n0 + wn0 + nt * 8 + t * 2;
                if ((g & 1) == 0 && col < NJ) {
                    int or0 = row >> 1;
                    int or1 = (row + 8) >> 1;
                    *reinterpret_cast<float2*>(&Pz[(size_t)or0 * NJ + col]) = make_float2(v0, v1);
                    *reinterpret_cast<float2*>(&Pz[(size_t)or1 * NJ + col]) = make_float2(v2, v3);
                }
            }
        }
    }
}

// ---------------- sum Z0 partial slices -> O0 (float4) ----------------
__global__ void sum2_kernel(const float* __restrict__ P, float* __restrict__ O, int n4) {
    int i = blockIdx.x * 256 + threadIdx.x;
    if (i >= n4) return;
    const float4* p = reinterpret_cast<const float4*>(P);
    float4 a = p[i];
    float4 b = p[i + n4];
    reinterpret_cast<float4*>(O)[i] =
        make_float4(a.x + b.x, a.y + b.y, a.z + b.z, a.w + b.w);
}

// ---------------- Final reduce: [B, 400] ----------------
__global__ void reduce_kernel(const float* __restrict__ out0,
                              const float* __restrict__ P1,
                              float* __restrict__ res)
{
    int i = blockIdx.x * 256 + threadIdx.x;
    if (i >= BATCH * 2 * NJ) return;
    int b = i / (2 * NJ), j = i % (2 * NJ);
    if (j < NJ) {
        float s = 0.f;
        #pragma unroll
        for (int k = 0; k < KDIM; k++)
            s += out0[(size_t)(b * KDIM + k) * NJ + j];
        res[i] = s;
    } else {
        float s = 0.f;
        #pragma unroll
        for (int z = 0; z < Z1; z++)
            s += P1[(size_t)z * BATCH * NJ + (size_t)b * NJ + (j - NJ)];
        res[i] = s;
    }
}

extern "C" void kernel_launch(void* const* d_in, const int* in_sizes, int n_in,
                              void* d_out, int out_size)
{
    const float* inp = (const float*)d_in[0];
    const float* wq0 = (const float*)d_in[1];
    const float* wk0 = (const float*)d_in[2];
    const float* wv0 = (const float*)d_in[3];
    const float* cw0 = (const float*)d_in[4];
    const float* wq1 = (const float*)d_in[5];
    const float* wk1 = (const float*)d_in[6];
    const float* wv1 = (const float*)d_in[7];
    const float* cw1 = (const float*)d_in[8];
    float* out = (float*)d_out;

    __nv_bfloat16 *A0, *Xp, *B0, *B1;
    float *P0, *P1, *O0;
    cudaGetSymbolAddress((void**)&A0, g_A0);
    cudaGetSymbolAddress((void**)&Xp, g_Xp);
    cudaGetSymbolAddress((void**)&B0, g_B0);
    cudaGetSymbolAddress((void**)&B1, g_B1);
    cudaGetSymbolAddress((void**)&P0, g_P0);
    cudaGetSymbolAddress((void**)&P1, g_P1);
    cudaGetSymbolAddress((void**)&O0, g_O0);

    cudaFuncSetAttribute(mma_gemm_kernel, cudaFuncAttributeMaxDynamicSharedMemorySize, 98304);

    // weight transpose + bf16 split
    bprep_kernel<<<dim3(C0 / 32, 8), 256>>>(cw0, B0, C0);
    bprep_kernel<<<dim3(C1 / 32, 8), 256>>>(cw1, B1, C1);

    // layer 0
    prep0_kernel<<<M0, 128>>>(inp, wq0, wk0, wv0, A0);
    // M=8192 (64 tiles), 2 n-tiles, nc=75 chunks, Z0=2 (cpz=38) -> 256 CTAs (1 wave @ 2/SM)
    mma_gemm_kernel<<<dim3(64, 2, Z0), 256, 98304>>>(A0, B0, P0, (size_t)M0 * NJ, C0, 38, 75, 0);
    sum2_kernel<<<(M0 * NJ / 4 + 255) / 256, 256>>>(P0, O0, M0 * NJ / 4);

    // layer 1 (k-presummed, split-g)
    prep1_kernel<<<2048, 256>>>(inp, O0, wq1, wk1, wv1, Xp);
    // M=512 (4 tiles), nc=375 chunks, Z1=37 (cpz=11) -> 296 CTAs (exactly 1 wave @ 2/SM)
    mma_gemm_kernel<<<dim3(4, 2, Z1), 256, 98304>>>(Xp, B1, P1, (size_t)BATCH * NJ, C1, 11, 375, 1);

    reduce_kernel<<<(BATCH * 2 * NJ + 255) / 256, 256>>>(O0, P1, out);
}

// round 7
// speedup vs baseline: 1.0763x; 1.0763x over previous
#include <cuda_runtime.h>
#include <cuda_bf16.h>
#include <cstdint>
#include <cstddef>

#define BATCH 256
#define F0    40
#define KDIM  32
#define NJ    200
#define C0    1600
#define C1    8000
#define M0    8192
#define KG    16
#define M1    512
#define Z0    4      // split-K slices layer 0
#define Z1    37     // split-K slices layer 1

// ---- scratch (static __device__, per harness rules) ----
__device__ __align__(16) __nv_bfloat16 g_A0[(size_t)M0 * 2 * C0];   // [8192, 3200]  hi|lo
__device__ __align__(16) __nv_bfloat16 g_Xp[(size_t)M1 * 2 * C1];   // [512, 16000]  hi|lo
__device__ __align__(16) __nv_bfloat16 g_B0[(size_t)256 * 2 * C0];  // [256, 3200]   hi|lo
__device__ __align__(16) __nv_bfloat16 g_B1[(size_t)256 * 2 * C1];  // [256, 16000]
__device__ __align__(16) float g_P0[(size_t)Z0 * M0 * NJ];          // gemm0 partials
__device__ __align__(16) float g_P1[(size_t)Z1 * BATCH * NJ];       // gemm1 partials
__device__ __align__(16) float g_O0[(size_t)M0 * NJ];               // summed out0

// ================= helpers =================
__device__ __forceinline__ uint32_t smem_u32(const void* p) {
    uint32_t a;
    asm("{ .reg .u64 t; cvta.to.shared.u64 t, %1; cvt.u32.u64 %0, t; }" : "=r"(a) : "l"(p));
    return a;
}

__device__ __forceinline__ void ldm_x4(uint32_t* r, uint32_t addr) {
    asm volatile("ldmatrix.sync.aligned.m8n8.x4.shared.b16 {%0,%1,%2,%3}, [%4];"
        : "=r"(r[0]), "=r"(r[1]), "=r"(r[2]), "=r"(r[3]) : "r"(addr));
}

__device__ __forceinline__ void mma_bf16(float* d, const uint32_t* a, uint32_t b0, uint32_t b1) {
    asm volatile("mma.sync.aligned.m16n8k16.row.col.f32.bf16.bf16.f32 "
        "{%0,%1,%2,%3}, {%4,%5,%6,%7}, {%8,%9}, {%0,%1,%2,%3};"
        : "+f"(d[0]), "+f"(d[1]), "+f"(d[2]), "+f"(d[3])
        : "r"(a[0]), "r"(a[1]), "r"(a[2]), "r"(a[3]), "r"(b0), "r"(b1));
}

__device__ __forceinline__ void cp16(uint32_t saddr, const void* gaddr) {
    asm volatile("cp.async.cg.shared.global [%0], [%1], 16;" :: "r"(saddr), "l"(gaddr));
}
__device__ __forceinline__ void cp_commit() { asm volatile("cp.async.commit_group;" ::: "memory"); }
__device__ __forceinline__ void cp_wait1()  { asm volatile("cp.async.wait_group 1;" ::: "memory"); }

__device__ __forceinline__ void split_store(__nv_bfloat16* hi_p, __nv_bfloat16* lo_p, float v) {
    __nv_bfloat16 h = __float2bfloat16(v);
    *hi_p = h;
    *lo_p = __float2bfloat16(v - __bfloat162float(h));
}

// ================= weight prep =================
__global__ void bprep_kernel(const float* __restrict__ cw, __nv_bfloat16* __restrict__ Bt, int C) {
    __shared__ float t[32][33];
    int cb = blockIdx.x * 32;
    int jb = blockIdx.y * 32;
    int tx = threadIdx.x & 31, ty = threadIdx.x >> 5;
    #pragma unroll
    for (int r = 0; r < 32; r += 8) {
        int c = cb + ty + r;
        int j = jb + tx;
        t[ty + r][tx] = (j < NJ) ? cw[(size_t)c * NJ + j] : 0.f;
    }
    __syncthreads();
    #pragma unroll
    for (int r = 0; r < 32; r += 8) {
        int j = jb + ty + r;
        int c = cb + tx;
        float v = t[tx][ty + r];
        split_store(&Bt[(size_t)j * (2 * C) + c], &Bt[(size_t)j * (2 * C) + C + c], v);
    }
}

// ---------------- Layer 0 producer -> A0 bf16 hi|lo ----------------
__global__ void __launch_bounds__(128) prep0_kernel(
    const float* __restrict__ inp, const float* __restrict__ wq,
    const float* __restrict__ wk, const float* __restrict__ wv,
    __nv_bfloat16* __restrict__ A0)
{
    __shared__ float u[F0], w[F0], v[F0], Sinv[F0];
    __shared__ float E[C0];
    int bk = blockIdx.x;
    int b = bk >> 5, k = bk & 31;
    int tid = threadIdx.x;

    if (tid < F0) {
        float x = inp[(size_t)(b * F0 + tid) * KDIM + k];
        u[tid] = x * wk[tid * KDIM + k];
        w[tid] = x * wv[tid * KDIM + k];
        v[tid] = x * wq[tid * KDIM + k];
    }
    __syncthreads();
    for (int idx = tid; idx < C0; idx += 128) {
        int f = idx / 40, g = idx - f * 40;
        E[idx] = __expf(u[f] * v[g]);
    }
    __syncthreads();
    if (tid < F0) {
        float s = 0.f;
        #pragma unroll
        for (int f = 0; f < F0; f++) s += E[f * 40 + tid];
        Sinv[tid] = 1.0f / s;
    }
    __syncthreads();
    __nv_bfloat16* rowp = A0 + (size_t)bk * (2 * C0);
    for (int idx = tid; idx < C0; idx += 128) {
        int f = idx / 40, g = idx - f * 40;
        float val = w[f] * E[idx] * Sinv[g];
        split_store(&rowp[idx], &rowp[C0 + idx], val);
    }
}

// ---------------- Layer 1 producer: split-g, register-accumulated ----------------
__global__ void __launch_bounds__(256) prep1_kernel(
    const float* __restrict__ inp, const float* __restrict__ out0,
    const float* __restrict__ wq, const float* __restrict__ wk,
    const float* __restrict__ wv, __nv_bfloat16* __restrict__ Xp)
{
    __shared__ float u[F0], w[F0], vl[50], Sinv[50];
    __shared__ float E[2000];
    const int blk = blockIdx.x;       // 2048
    const int gq = blk & 3;
    const int bk2 = blk >> 2;
    const int kg = bk2 & 1;
    const int b = bk2 >> 1;
    const int tid = threadIdx.x;
    const int gbase = gq * 50;

    int fi[8], gi[8];
    bool ok[8];
    float acc[8];
    #pragma unroll
    for (int i = 0; i < 8; i++) {
        int id = tid + 256 * i;
        ok[i] = (id < 2000);
        int idc = ok[i] ? id : 0;
        fi[i] = idc / 50;
        gi[i] = idc - fi[i] * 50;
        acc[i] = 0.f;
    }

    for (int kk = 0; kk < KG; kk++) {
        int k = kg * KG + kk;
        __syncthreads();
        if (tid < F0) {
            float x = inp[(size_t)(b * F0 + tid) * KDIM + k];
            u[tid] = x * wk[tid * KDIM + k];
            w[tid] = x * wv[tid * KDIM + k];
        }
        if (tid >= 64 && tid < 114) {
            int g = tid - 64;
            vl[g] = out0[(size_t)(b * KDIM + k) * NJ + gbase + g] * wq[(gbase + g) * KDIM + k];
        }
        __syncthreads();
        float e[8];
        #pragma unroll
        for (int i = 0; i < 8; i++) {
            e[i] = __expf(u[fi[i]] * vl[gi[i]]);
            if (ok[i]) E[tid + 256 * i] = e[i];
        }
        __syncthreads();
        if (tid < 50) {
            float s = 0.f;
            #pragma unroll
            for (int f = 0; f < F0; f++) s += E[f * 50 + tid];
            Sinv[tid] = 1.0f / s;
        }
        __syncthreads();
        #pragma unroll
        for (int i = 0; i < 8; i++)
            acc[i] += w[fi[i]] * e[i] * Sinv[gi[i]];
    }

    __nv_bfloat16* rowp = Xp + (size_t)(b * 2 + kg) * (2 * C1);
    #pragma unroll
    for (int i = 0; i < 8; i++) {
        if (!ok[i]) continue;
        int c = fi[i] * NJ + gbase + gi[i];
        split_store(&rowp[c], &rowp[C1 + c], acc[i]);
    }
}

// ---------------- mma.sync bf16x3 GEMM body, compile-time NV specialization ----
// NV = valid output columns in this n-tile (128 for n0=0, 72 for n0=128).
// All loop trip counts are compile-time; edge warp (wn0=64, NV=72) runs a
// separate fully-unrolled 1-chunk path. No runtime guards in the hot loop.
template<int NV>
__device__ __forceinline__ void gemm_body(
    const __nv_bfloat16* __restrict__ A,
    const __nv_bfloat16* __restrict__ B,
    float* __restrict__ P, size_t sliceStride,
    int K, int cpz, int nc, int fold, char* sm)
{
    constexpr int n0 = (NV == 128) ? 0 : 128;
    constexpr int brows = (NV >= 128) ? 128 : ((NV + 15) & ~15);   // 128 or 80
    const int tid = threadIdx.x;
    const int lane = tid & 31;
    const int wid = tid >> 5;
    const int wm0 = (wid & 3) * 32;
    const int wn0 = (wid >> 2) * 64;
    const int m0 = blockIdx.x * 128;
    const int cpk = K / 64;
    const int lda = 2 * K;
    const int c0 = blockIdx.z * cpz;
    int c1 = c0 + cpz; if (c1 > nc) c1 = nc;

    const uint32_t sb = smem_u32(sm);
    float* Pz = P + (size_t)blockIdx.z * sliceStride;

    float acc[2][8][4];
    #pragma unroll
    for (int i = 0; i < 2; i++)
        #pragma unroll
        for (int j = 0; j < 8; j++)
            #pragma unroll
            for (int l = 0; l < 4; l++) acc[i][j][l] = 0.f;

    auto gissue = [&](int c, int st) {
        int region = c / cpk;
        int within = c - region * cpk;
        int acol = (region == 1 ? K : 0) + within * 64;
        int bcol = (region == 2 ? K : 0) + within * 64;
        uint32_t abase = sb + st * 32768;
        uint32_t bbase = abase + 16384;
        #pragma unroll
        for (int i = 0; i < 4; i++) {
            int idx = tid + 256 * i;
            int row = idx >> 3, q = idx & 7;
            cp16(abase + (row * 8 + (q ^ (row & 7))) * 16,
                 A + (size_t)(m0 + row) * lda + acol + q * 8);
        }
        #pragma unroll
        for (int i = 0; i < 4; i++) {
            int idx = tid + 256 * i;
            int row = idx >> 3, q = idx & 7;
            if (row < brows)     // compile-time bound
                cp16(bbase + (row * 8 + (q ^ (row & 7))) * 16,
                     B + (size_t)(n0 + row) * lda + bcol + q * 8);
        }
        cp_commit();
    };

    if (c0 < c1) gissue(c0, 0); else cp_commit();
    if (c0 + 1 < c1) gissue(c0 + 1, 1); else cp_commit();

    const int t3 = lane >> 3;
    const int r8 = lane & 7;
    const bool fullwarp = (NV >= 128) || (wn0 == 0);

    for (int c = c0; c < c1; c++) {
        int rel = c - c0;
        int st = rel % 3;
        cp_wait1();
        __syncthreads();
        if (c + 2 < c1) gissue(c + 2, (rel + 2) % 3);
        uint32_t ab = sb + st * 32768;
        uint32_t bb = ab + 16384;
        #pragma unroll
        for (int ks = 0; ks < 4; ks++) {
            int kc = ks * 2;
            uint32_t afr[2][4], bfr[4][4];
            #pragma unroll
            for (int mt = 0; mt < 2; mt++) {
                int m = wm0 + mt * 16 + (t3 & 1) * 8 + r8;
                int q = kc + (t3 >> 1);
                ldm_x4(afr[mt], ab + (m * 8 + (q ^ (m & 7))) * 16);
            }
            if (fullwarp) {
                #pragma unroll
                for (int np = 0; np < 4; np++) {
                    int n = wn0 + np * 16 + (t3 >> 1) * 8 + r8;
                    int q = kc + (t3 & 1);
                    ldm_x4(bfr[np], bb + (n * 8 + (q ^ (n & 7))) * 16);
                }
                #pragma unroll
                for (int mt = 0; mt < 2; mt++)
                    #pragma unroll
                    for (int nt = 0; nt < 8; nt++)
                        mma_bf16(acc[mt][nt], afr[mt],
                                 bfr[nt >> 1][(nt & 1) * 2], bfr[nt >> 1][(nt & 1) * 2 + 1]);
            } else {
                // edge warp: single 16-row n-chunk (cols 64..79 of tile; only 64..71 valid)
                int n = wn0 + (t3 >> 1) * 8 + r8;
                int q = kc + (t3 & 1);
                ldm_x4(bfr[0], bb + (n * 8 + (q ^ (n & 7))) * 16);
                #pragma unroll
                for (int mt = 0; mt < 2; mt++)
                    mma_bf16(acc[mt][0], afr[mt], bfr[0][0], bfr[0][1]);
            }
        }
    }

    // epilogue: plain vectorized stores into this z-slice
    const int g = lane >> 2, t = lane & 3;
    if (!fold) {
        #pragma unroll
        for (int mt = 0; mt < 2; mt++) {
            #pragma unroll
            for (int nt = 0; nt < 8; nt++) {
                int row = m0 + wm0 + mt * 16 + g;
                int col = n0 + wn0 + nt * 8 + t * 2;
                if (col < NJ) {
                    *reinterpret_cast<float2*>(&Pz[(size_t)row * NJ + col]) =
                        make_float2(acc[mt][nt][0], acc[mt][nt][1]);
                    *reinterpret_cast<float2*>(&Pz[(size_t)(row + 8) * NJ + col]) =
                        make_float2(acc[mt][nt][2], acc[mt][nt][3]);
                }
            }
        }
    } else {
        #pragma unroll
        for (int mt = 0; mt < 2; mt++) {
            #pragma unroll
            for (int nt = 0; nt < 8; nt++) {
                float v0 = acc[mt][nt][0] + __shfl_xor_sync(0xFFFFFFFFu, acc[mt][nt][0], 4);
                float v1 = acc[mt][nt][1] + __shfl_xor_sync(0xFFFFFFFFu, acc[mt][nt][1], 4);
                float v2 = acc[mt][nt][2] + __shfl_xor_sync(0xFFFFFFFFu, acc[mt][nt][2], 4);
                float v3 = acc[mt][nt][3] + __shfl_xor_sync(0xFFFFFFFFu, acc[mt][nt][3], 4);
                int row = m0 + wm0 + mt * 16 + g;
                int col = n0 + wn0 + nt * 8 + t * 2;
                if ((g & 1) == 0 && col < NJ) {
                    int or0 = row >> 1;
                    int or1 = (row + 8) >> 1;
                    *reinterpret_cast<float2*>(&Pz[(size_t)or0 * NJ + col]) = make_float2(v0, v1);
                    *reinterpret_cast<float2*>(&Pz[(size_t)or1 * NJ + col]) = make_float2(v2, v3);
                }
            }
        }
    }
}

__global__ void __launch_bounds__(256, 2) mma_gemm_kernel(
    const __nv_bfloat16* __restrict__ A,
    const __nv_bfloat16* __restrict__ B,
    float* __restrict__ P, size_t sliceStride,
    int K, int cpz, int nc, int fold)
{
    extern __shared__ char sm[];       // 3 stages x (A 16KB + B 16KB) = 96KB
    if (blockIdx.y == 0)
        gemm_body<128>(A, B, P, sliceStride, K, cpz, nc, fold, sm);
    else
        gemm_body<72>(A, B, P, sliceStride, K, cpz, nc, fold, sm);
}

// ---------------- sum Z0 partial slices -> O0 (float4) ----------------
__global__ void sum4_kernel(const float* __restrict__ P, float* __restrict__ O, int n4) {
    int i = blockIdx.x * 256 + threadIdx.x;
    if (i >= n4) return;
    const float4* p = reinterpret_cast<const float4*>(P);
    float4 a = p[i];
    float4 b = p[i + n4];
    float4 c = p[i + 2 * n4];
    float4 d = p[i + 3 * n4];
    reinterpret_cast<float4*>(O)[i] =
        make_float4(a.x + b.x + c.x + d.x, a.y + b.y + c.y + d.y,
                    a.z + b.z + c.z + d.z, a.w + b.w + c.w + d.w);
}

// ---------------- Final reduce: [B, 400] ----------------
__global__ void reduce_kernel(const float* __restrict__ out0,
                              const float* __restrict__ P1,
                              float* __restrict__ res)
{
    int i = blockIdx.x * 256 + threadIdx.x;
    if (i >= BATCH * 2 * NJ) return;
    int b = i / (2 * NJ), j = i % (2 * NJ);
    if (j < NJ) {
        float s = 0.f;
        #pragma unroll
        for (int k = 0; k < KDIM; k++)
            s += out0[(size_t)(b * KDIM + k) * NJ + j];
        res[i] = s;
    } else {
        float s = 0.f;
        #pragma unroll
        for (int z = 0; z < Z1; z++)
            s += P1[(size_t)z * BATCH * NJ + (size_t)b * NJ + (j - NJ)];
        res[i] = s;
    }
}

extern "C" void kernel_launch(void* const* d_in, const int* in_sizes, int n_in,
                              void* d_out, int out_size)
{
    const float* inp = (const float*)d_in[0];
    const float* wq0 = (const float*)d_in[1];
    const float* wk0 = (const float*)d_in[2];
    const float* wv0 = (const float*)d_in[3];
    const float* cw0 = (const float*)d_in[4];
    const float* wq1 = (const float*)d_in[5];
    const float* wk1 = (const float*)d_in[6];
    const float* wv1 = (const float*)d_in[7];
    const float* cw1 = (const float*)d_in[8];
    float* out = (float*)d_out;

    __nv_bfloat16 *A0, *Xp, *B0, *B1;
    float *P0, *P1, *O0;
    cudaGetSymbolAddress((void**)&A0, g_A0);
    cudaGetSymbolAddress((void**)&Xp, g_Xp);
    cudaGetSymbolAddress((void**)&B0, g_B0);
    cudaGetSymbolAddress((void**)&B1, g_B1);
    cudaGetSymbolAddress((void**)&P0, g_P0);
    cudaGetSymbolAddress((void**)&P1, g_P1);
    cudaGetSymbolAddress((void**)&O0, g_O0);

    cudaFuncSetAttribute(mma_gemm_kernel, cudaFuncAttributeMaxDynamicSharedMemorySize, 98304);

    // weight transpose + bf16 split
    bprep_kernel<<<dim3(C0 / 32, 8), 256>>>(cw0, B0, C0);
    bprep_kernel<<<dim3(C1 / 32, 8), 256>>>(cw1, B1, C1);

    // layer 0
    prep0_kernel<<<M0, 128>>>(inp, wq0, wk0, wv0, A0);
    // M=8192 (64 tiles), 2 n-tiles (compile-time specialized), nc=75, Z0=4 (cpz=19)
    mma_gemm_kernel<<<dim3(64, 2, Z0), 256, 98304>>>(A0, B0, P0, (size_t)M0 * NJ, C0, 19, 75, 0);
    sum4_kernel<<<(M0 * NJ / 4 + 255) / 256, 256>>>(P0, O0, M0 * NJ / 4);

    // layer 1 (k-presummed, split-g)
    prep1_kernel<<<2048, 256>>>(inp, O0, wq1, wk1, wv1, Xp);
    // M=512 (4 tiles), nc=375 chunks, Z1=37 (cpz=11) -> 296 CTAs (1 full wave @ 2/SM)
    mma_gemm_kernel<<<dim3(4, 2, Z1), 256, 98304>>>(Xp, B1, P1, (size_t)BATCH * NJ, C1, 11, 375, 1);

    reduce_kernel<<<(BATCH * 2 * NJ + 255) / 256, 256>>>(O0, P1, out);
}

// round 8
// speedup vs baseline: 1.4564x; 1.3531x over previous
#include <cuda_runtime.h>
#include <cuda_bf16.h>
#include <cstdint>
#include <cstddef>

#define BATCH 256
#define F0    40
#define KDIM  32
#define NJ    200
#define C0    1600
#define C1    8000
#define M0    8192
#define KG    16
#define M1    512
#define Z0    4      // split-K slices layer 0
#define Z1    37     // split-K slices layer 1

// ---- scratch (static __device__, per harness rules) ----
__device__ __align__(16) __nv_bfloat16 g_A0[(size_t)M0 * 2 * C0];   // [8192, 3200]  hi|lo
__device__ __align__(16) __nv_bfloat16 g_Xp[(size_t)M1 * 2 * C1];   // [512, 16000]  hi|lo
__device__ __align__(16) __nv_bfloat16 g_B0[(size_t)256 * 2 * C0];  // [256, 3200]   hi|lo
__device__ __align__(16) __nv_bfloat16 g_B1[(size_t)256 * 2 * C1];  // [256, 16000]
__device__ __align__(16) float g_P0[(size_t)Z0 * M0 * NJ];          // gemm0 partials
__device__ __align__(16) float g_P1[(size_t)Z1 * BATCH * NJ];       // gemm1 partials
__device__ __align__(16) float g_O0[(size_t)M0 * NJ];               // summed out0

// ================= helpers =================
__device__ __forceinline__ uint32_t smem_u32(const void* p) {
    uint32_t a;
    asm("{ .reg .u64 t; cvta.to.shared.u64 t, %1; cvt.u32.u64 %0, t; }" : "=r"(a) : "l"(p));
    return a;
}

__device__ __forceinline__ void ldm_x4(uint32_t* r, uint32_t addr) {
    asm volatile("ldmatrix.sync.aligned.m8n8.x4.shared.b16 {%0,%1,%2,%3}, [%4];"
        : "=r"(r[0]), "=r"(r[1]), "=r"(r[2]), "=r"(r[3]) : "r"(addr));
}

__device__ __forceinline__ void mma_bf16(float* d, const uint32_t* a, uint32_t b0, uint32_t b1) {
    asm volatile("mma.sync.aligned.m16n8k16.row.col.f32.bf16.bf16.f32 "
        "{%0,%1,%2,%3}, {%4,%5,%6,%7}, {%8,%9}, {%0,%1,%2,%3};"
        : "+f"(d[0]), "+f"(d[1]), "+f"(d[2]), "+f"(d[3])
        : "r"(a[0]), "r"(a[1]), "r"(a[2]), "r"(a[3]), "r"(b0), "r"(b1));
}

__device__ __forceinline__ void cp16(uint32_t saddr, const void* gaddr) {
    asm volatile("cp.async.cg.shared.global [%0], [%1], 16;" :: "r"(saddr), "l"(gaddr));
}
__device__ __forceinline__ void cp_commit() { asm volatile("cp.async.commit_group;" ::: "memory"); }
__device__ __forceinline__ void cp_wait1()  { asm volatile("cp.async.wait_group 1;" ::: "memory"); }

__device__ __forceinline__ void split_store(__nv_bfloat16* hi_p, __nv_bfloat16* lo_p, float v) {
    __nv_bfloat16 h = __float2bfloat16(v);
    *hi_p = h;
    *lo_p = __float2bfloat16(v - __bfloat162float(h));
}

// ================= weight prep =================
__global__ void bprep_kernel(const float* __restrict__ cw, __nv_bfloat16* __restrict__ Bt, int C) {
    __shared__ float t[32][33];
    int cb = blockIdx.x * 32;
    int jb = blockIdx.y * 32;
    int tx = threadIdx.x & 31, ty = threadIdx.x >> 5;
    #pragma unroll
    for (int r = 0; r < 32; r += 8) {
        int c = cb + ty + r;
        int j = jb + tx;
        t[ty + r][tx] = (j < NJ) ? cw[(size_t)c * NJ + j] : 0.f;
    }
    __syncthreads();
    #pragma unroll
    for (int r = 0; r < 32; r += 8) {
        int j = jb + ty + r;
        int c = cb + tx;
        float v = t[tx][ty + r];
        split_store(&Bt[(size_t)j * (2 * C) + c], &Bt[(size_t)j * (2 * C) + C + c], v);
    }
}

// ---------------- Layer 0 producer -> A0 bf16 hi|lo ----------------
__global__ void __launch_bounds__(128) prep0_kernel(
    const float* __restrict__ inp, const float* __restrict__ wq,
    const float* __restrict__ wk, const float* __restrict__ wv,
    __nv_bfloat16* __restrict__ A0)
{
    __shared__ float u[F0], w[F0], v[F0], Sinv[F0];
    __shared__ float E[C0];
    int bk = blockIdx.x;
    int b = bk >> 5, k = bk & 31;
    int tid = threadIdx.x;

    if (tid < F0) {
        float x = inp[(size_t)(b * F0 + tid) * KDIM + k];
        u[tid] = x * wk[tid * KDIM + k];
        w[tid] = x * wv[tid * KDIM + k];
        v[tid] = x * wq[tid * KDIM + k];
    }
    __syncthreads();
    for (int idx = tid; idx < C0; idx += 128) {
        int f = idx / 40, g = idx - f * 40;
        E[idx] = __expf(u[f] * v[g]);
    }
    __syncthreads();
    if (tid < F0) {
        float s = 0.f;
        #pragma unroll
        for (int f = 0; f < F0; f++) s += E[f * 40 + tid];
        Sinv[tid] = 1.0f / s;
    }
    __syncthreads();
    __nv_bfloat16* rowp = A0 + (size_t)bk * (2 * C0);
    for (int idx = tid; idx < C0; idx += 128) {
        int f = idx / 40, g = idx - f * 40;
        float val = w[f] * E[idx] * Sinv[g];
        split_store(&rowp[idx], &rowp[C0 + idx], val);
    }
}

// ---------------- Layer 1 producer: column-owned, barrier-free main loop ------
// block = (b, kg) : 512 blocks x 256 threads. Thread g (< 200) owns output
// column g across all f; accumulates over KG k-slots entirely in registers.
// One __syncthreads total (after staging u/w).
__global__ void __launch_bounds__(256) prep1_kernel(
    const float* __restrict__ inp, const float* __restrict__ out0,
    const float* __restrict__ wq, const float* __restrict__ wk,
    const float* __restrict__ wv, __nv_bfloat16* __restrict__ Xp)
{
    __shared__ float u[KG][F0], w[KG][F0];
    const int blk = blockIdx.x;       // 512 = b*2 + kg
    const int kg = blk & 1;
    const int b = blk >> 1;
    const int tid = threadIdx.x;

    // stage u,w for all KG k-slots (640 entries each)
    for (int i = tid; i < KG * F0; i += 256) {
        int kk = i / F0, f = i - kk * F0;
        int k = kg * KG + kk;
        float x = inp[(size_t)(b * F0 + f) * KDIM + k];
        u[kk][f] = x * wk[f * KDIM + k];
        w[kk][f] = x * wv[f * KDIM + k];
    }
    __syncthreads();

    if (tid >= NJ) return;            // no further barriers: safe
    const int g = tid;

    float acc[F0];
    #pragma unroll
    for (int f = 0; f < F0; f++) acc[f] = 0.f;

    for (int kk = 0; kk < KG; kk++) {
        int k = kg * KG + kk;
        float v = out0[(size_t)(b * KDIM + k) * NJ + g] * wq[g * KDIM + k];
        float e[F0];
        float s = 0.f;
        #pragma unroll
        for (int f = 0; f < F0; f++) {
            e[f] = __expf(u[kk][f] * v);
            s += e[f];
        }
        float sinv = 1.0f / s;
        #pragma unroll
        for (int f = 0; f < F0; f++)
            acc[f] += w[kk][f] * e[f] * sinv;
    }

    __nv_bfloat16* rowp = Xp + (size_t)blk * (2 * C1);
    #pragma unroll
    for (int f = 0; f < F0; f++) {
        int c = f * NJ + g;
        split_store(&rowp[c], &rowp[C1 + c], acc[f]);
    }
}

// ---------------- mma.sync bf16x3 GEMM body, compile-time NV specialization ----
template<int NV>
__device__ __forceinline__ void gemm_body(
    const __nv_bfloat16* __restrict__ A,
    const __nv_bfloat16* __restrict__ B,
    float* __restrict__ P, size_t sliceStride,
    int K, int cpz, int nc, int fold, char* sm)
{
    constexpr int n0 = (NV == 128) ? 0 : 128;
    constexpr int brows = (NV >= 128) ? 128 : ((NV + 15) & ~15);   // 128 or 80
    const int tid = threadIdx.x;
    const int lane = tid & 31;
    const int wid = tid >> 5;
    const int wm0 = (wid & 3) * 32;
    const int wn0 = (wid >> 2) * 64;
    const int m0 = blockIdx.x * 128;
    const int cpk = K / 64;
    const int lda = 2 * K;
    const int c0 = blockIdx.z * cpz;
    int c1 = c0 + cpz; if (c1 > nc) c1 = nc;

    const uint32_t sb = smem_u32(sm);
    float* Pz = P + (size_t)blockIdx.z * sliceStride;

    float acc[2][8][4];
    #pragma unroll
    for (int i = 0; i < 2; i++)
        #pragma unroll
        for (int j = 0; j < 8; j++)
            #pragma unroll
            for (int l = 0; l < 4; l++) acc[i][j][l] = 0.f;

    auto gissue = [&](int c, int st) {
        int region = c / cpk;
        int within = c - region * cpk;
        int acol = (region == 1 ? K : 0) + within * 64;
        int bcol = (region == 2 ? K : 0) + within * 64;
        uint32_t abase = sb + st * 32768;
        uint32_t bbase = abase + 16384;
        #pragma unroll
        for (int i = 0; i < 4; i++) {
            int idx = tid + 256 * i;
            int row = idx >> 3, q = idx & 7;
            cp16(abase + (row * 8 + (q ^ (row & 7))) * 16,
                 A + (size_t)(m0 + row) * lda + acol + q * 8);
        }
        #pragma unroll
        for (int i = 0; i < 4; i++) {
            int idx = tid + 256 * i;
            int row = idx >> 3, q = idx & 7;
            if (row < brows)     // compile-time bound
                cp16(bbase + (row * 8 + (q ^ (row & 7))) * 16,
                     B + (size_t)(n0 + row) * lda + bcol + q * 8);
        }
        cp_commit();
    };

    if (c0 < c1) gissue(c0, 0); else cp_commit();
    if (c0 + 1 < c1) gissue(c0 + 1, 1); else cp_commit();

    const int t3 = lane >> 3;
    const int r8 = lane & 7;
    const bool fullwarp = (NV >= 128) || (wn0 == 0);

    for (int c = c0; c < c1; c++) {
        int rel = c - c0;
        int st = rel % 3;
        cp_wait1();
        __syncthreads();
        if (c + 2 < c1) gissue(c + 2, (rel + 2) % 3);
        uint32_t ab = sb + st * 32768;
        uint32_t bb = ab + 16384;
        #pragma unroll
        for (int ks = 0; ks < 4; ks++) {
            int kc = ks * 2;
            uint32_t afr[2][4], bfr[4][4];
            #pragma unroll
            for (int mt = 0; mt < 2; mt++) {
                int m = wm0 + mt * 16 + (t3 & 1) * 8 + r8;
                int q = kc + (t3 >> 1);
                ldm_x4(afr[mt], ab + (m * 8 + (q ^ (m & 7))) * 16);
            }
            if (fullwarp) {
                #pragma unroll
                for (int np = 0; np < 4; np++) {
                    int n = wn0 + np * 16 + (t3 >> 1) * 8 + r8;
                    int q = kc + (t3 & 1);
                    ldm_x4(bfr[np], bb + (n * 8 + (q ^ (n & 7))) * 16);
                }
                #pragma unroll
                for (int mt = 0; mt < 2; mt++)
                    #pragma unroll
                    for (int nt = 0; nt < 8; nt++)
                        mma_bf16(acc[mt][nt], afr[mt],
                                 bfr[nt >> 1][(nt & 1) * 2], bfr[nt >> 1][(nt & 1) * 2 + 1]);
            } else {
                int n = wn0 + (t3 >> 1) * 8 + r8;
                int q = kc + (t3 & 1);
                ldm_x4(bfr[0], bb + (n * 8 + (q ^ (n & 7))) * 16);
                #pragma unroll
                for (int mt = 0; mt < 2; mt++)
                    mma_bf16(acc[mt][0], afr[mt], bfr[0][0], bfr[0][1]);
            }
        }
    }

    // epilogue: plain vectorized stores into this z-slice
    const int g = lane >> 2, t = lane & 3;
    if (!fold) {
        #pragma unroll
        for (int mt = 0; mt < 2; mt++) {
            #pragma unroll
            for (int nt = 0; nt < 8; nt++) {
                int row = m0 + wm0 + mt * 16 + g;
                int col = n0 + wn0 + nt * 8 + t * 2;
                if (col < NJ) {
                    *reinterpret_cast<float2*>(&Pz[(size_t)row * NJ + col]) =
                        make_float2(acc[mt][nt][0], acc[mt][nt][1]);
                    *reinterpret_cast<float2*>(&Pz[(size_t)(row + 8) * NJ + col]) =
                        make_float2(acc[mt][nt][2], acc[mt][nt][3]);
                }
            }
        }
    } else {
        #pragma unroll
        for (int mt = 0; mt < 2; mt++) {
            #pragma unroll
            for (int nt = 0; nt < 8; nt++) {
                float v0 = acc[mt][nt][0] + __shfl_xor_sync(0xFFFFFFFFu, acc[mt][nt][0], 4);
                float v1 = acc[mt][nt][1] + __shfl_xor_sync(0xFFFFFFFFu, acc[mt][nt][1], 4);
                float v2 = acc[mt][nt][2] + __shfl_xor_sync(0xFFFFFFFFu, acc[mt][nt][2], 4);
                float v3 = acc[mt][nt][3] + __shfl_xor_sync(0xFFFFFFFFu, acc[mt][nt][3], 4);
                int row = m0 + wm0 + mt * 16 + g;
                int col = n0 + wn0 + nt * 8 + t * 2;
                if ((g & 1) == 0 && col < NJ) {
                    int or0 = row >> 1;
                    int or1 = (row + 8) >> 1;
                    *reinterpret_cast<float2*>(&Pz[(size_t)or0 * NJ + col]) = make_float2(v0, v1);
                    *reinterpret_cast<float2*>(&Pz[(size_t)or1 * NJ + col]) = make_float2(v2, v3);
                }
            }
        }
    }
}

__global__ void __launch_bounds__(256, 2) mma_gemm_kernel(
    const __nv_bfloat16* __restrict__ A,
    const __nv_bfloat16* __restrict__ B,
    float* __restrict__ P, size_t sliceStride,
    int K, int cpz, int nc, int fold)
{
    extern __shared__ char sm[];       // 3 stages x (A 16KB + B 16KB) = 96KB
    if (blockIdx.y == 0)
        gemm_body<128>(A, B, P, sliceStride, K, cpz, nc, fold, sm);
    else
        gemm_body<72>(A, B, P, sliceStride, K, cpz, nc, fold, sm);
}

// ---------------- sum Z0 partial slices -> O0 (float4) ----------------
__global__ void sum4_kernel(const float* __restrict__ P, float* __restrict__ O, int n4) {
    int i = blockIdx.x * 256 + threadIdx.x;
    if (i >= n4) return;
    const float4* p = reinterpret_cast<const float4*>(P);
    float4 a = p[i];
    float4 b = p[i + n4];
    float4 c = p[i + 2 * n4];
    float4 d = p[i + 3 * n4];
    reinterpret_cast<float4*>(O)[i] =
        make_float4(a.x + b.x + c.x + d.x, a.y + b.y + c.y + d.y,
                    a.z + b.z + c.z + d.z, a.w + b.w + c.w + d.w);
}

// ---------------- Final reduce: [B, 400] ----------------
__global__ void reduce_kernel(const float* __restrict__ out0,
                              const float* __restrict__ P1,
                              float* __restrict__ res)
{
    int i = blockIdx.x * 256 + threadIdx.x;
    if (i >= BATCH * 2 * NJ) return;
    int b = i / (2 * NJ), j = i % (2 * NJ);
    if (j < NJ) {
        float s = 0.f;
        #pragma unroll
        for (int k = 0; k < KDIM; k++)
            s += out0[(size_t)(b * KDIM + k) * NJ + j];
        res[i] = s;
    } else {
        float s = 0.f;
        #pragma unroll
        for (int z = 0; z < Z1; z++)
            s += P1[(size_t)z * BATCH * NJ + (size_t)b * NJ + (j - NJ)];
        res[i] = s;
    }
}

extern "C" void kernel_launch(void* const* d_in, const int* in_sizes, int n_in,
                              void* d_out, int out_size)
{
    const float* inp = (const float*)d_in[0];
    const float* wq0 = (const float*)d_in[1];
    const float* wk0 = (const float*)d_in[2];
    const float* wv0 = (const float*)d_in[3];
    const float* cw0 = (const float*)d_in[4];
    const float* wq1 = (const float*)d_in[5];
    const float* wk1 = (const float*)d_in[6];
    const float* wv1 = (const float*)d_in[7];
    const float* cw1 = (const float*)d_in[8];
    float* out = (float*)d_out;

    __nv_bfloat16 *A0, *Xp, *B0, *B1;
    float *P0, *P1, *O0;
    cudaGetSymbolAddress((void**)&A0, g_A0);
    cudaGetSymbolAddress((void**)&Xp, g_Xp);
    cudaGetSymbolAddress((void**)&B0, g_B0);
    cudaGetSymbolAddress((void**)&B1, g_B1);
    cudaGetSymbolAddress((void**)&P0, g_P0);
    cudaGetSymbolAddress((void**)&P1, g_P1);
    cudaGetSymbolAddress((void**)&O0, g_O0);

    cudaFuncSetAttribute(mma_gemm_kernel, cudaFuncAttributeMaxDynamicSharedMemorySize, 98304);

    // weight transpose + bf16 split
    bprep_kernel<<<dim3(C0 / 32, 8), 256>>>(cw0, B0, C0);
    bprep_kernel<<<dim3(C1 / 32, 8), 256>>>(cw1, B1, C1);

    // layer 0
    prep0_kernel<<<M0, 128>>>(inp, wq0, wk0, wv0, A0);
    // M=8192 (64 tiles), 2 n-tiles (compile-time specialized), nc=75, Z0=4 (cpz=19)
    mma_gemm_kernel<<<dim3(64, 2, Z0), 256, 98304>>>(A0, B0, P0, (size_t)M0 * NJ, C0, 19, 75, 0);
    sum4_kernel<<<(M0 * NJ / 4 + 255) / 256, 256>>>(P0, O0, M0 * NJ / 4);

    // layer 1 (k-presummed, column-owned producer)
    prep1_kernel<<<M1, 256>>>(inp, O0, wq1, wk1, wv1, Xp);
    // M=512 (4 tiles), nc=375 chunks, Z1=37 (cpz=11) -> 296 CTAs (1 full wave @ 2/SM)
    mma_gemm_kernel<<<dim3(4, 2, Z1), 256, 98304>>>(Xp, B1, P1, (size_t)BATCH * NJ, C1, 11, 375, 1);

    reduce_kernel<<<(BATCH * 2 * NJ + 255) / 256, 256>>>(O0, P1, out);
}

// round 9
// speedup vs baseline: 1.5580x; 1.0698x over previous
#include <cuda_runtime.h>
#include <cuda_bf16.h>
#include <cstdint>
#include <cstddef>

#define BATCH 256
#define F0    40
#define KDIM  32
#define NJ    200
#define C0    1600
#define C1    8000
#define M0    8192
#define KG    16
#define M1    512
#define Z0    4      // split-K slices layer 0
#define Z1    37     // split-K slices layer 1

// ---- scratch (static __device__, per harness rules) ----
__device__ __align__(16) __nv_bfloat16 g_A0[(size_t)M0 * 2 * C0];   // [8192, 3200]  hi|lo
__device__ __align__(16) __nv_bfloat16 g_Xp[(size_t)M1 * 2 * C1];   // [512, 16000]  hi|lo
__device__ __align__(16) __nv_bfloat16 g_B0[(size_t)256 * 2 * C0];  // [256, 3200]   hi|lo
__device__ __align__(16) __nv_bfloat16 g_B1[(size_t)256 * 2 * C1];  // [256, 16000]
__device__ __align__(16) float g_P0[(size_t)Z0 * M0 * NJ];          // gemm0 partials
__device__ __align__(16) float g_P1[(size_t)Z1 * BATCH * NJ];       // gemm1 partials
__device__ __align__(16) float g_O0[(size_t)M0 * NJ];               // summed out0

// ================= helpers =================
__device__ __forceinline__ uint32_t smem_u32(const void* p) {
    uint32_t a;
    asm("{ .reg .u64 t; cvta.to.shared.u64 t, %1; cvt.u32.u64 %0, t; }" : "=r"(a) : "l"(p));
    return a;
}

__device__ __forceinline__ float ex2(float x) {
    float y;
    asm("ex2.approx.ftz.f32 %0, %1;" : "=f"(y) : "f"(x));
    return y;
}

__device__ __forceinline__ void ldm_x4(uint32_t* r, uint32_t addr) {
    asm volatile("ldmatrix.sync.aligned.m8n8.x4.shared.b16 {%0,%1,%2,%3}, [%4];"
        : "=r"(r[0]), "=r"(r[1]), "=r"(r[2]), "=r"(r[3]) : "r"(addr));
}

__device__ __forceinline__ void mma_bf16(float* d, const uint32_t* a, uint32_t b0, uint32_t b1) {
    asm volatile("mma.sync.aligned.m16n8k16.row.col.f32.bf16.bf16.f32 "
        "{%0,%1,%2,%3}, {%4,%5,%6,%7}, {%8,%9}, {%0,%1,%2,%3};"
        : "+f"(d[0]), "+f"(d[1]), "+f"(d[2]), "+f"(d[3])
        : "r"(a[0]), "r"(a[1]), "r"(a[2]), "r"(a[3]), "r"(b0), "r"(b1));
}

__device__ __forceinline__ void cp16(uint32_t saddr, const void* gaddr) {
    asm volatile("cp.async.cg.shared.global [%0], [%1], 16;" :: "r"(saddr), "l"(gaddr));
}
__device__ __forceinline__ void cp_commit() { asm volatile("cp.async.commit_group;" ::: "memory"); }
__device__ __forceinline__ void cp_wait1()  { asm volatile("cp.async.wait_group 1;" ::: "memory"); }

__device__ __forceinline__ void split_store(__nv_bfloat16* hi_p, __nv_bfloat16* lo_p, float v) {
    __nv_bfloat16 h = __float2bfloat16(v);
    *hi_p = h;
    *lo_p = __float2bfloat16(v - __bfloat162float(h));
}

// ================= weight prep =================
__global__ void bprep_kernel(const float* __restrict__ cw, __nv_bfloat16* __restrict__ Bt, int C) {
    __shared__ float t[32][33];
    int cb = blockIdx.x * 32;
    int jb = blockIdx.y * 32;
    int tx = threadIdx.x & 31, ty = threadIdx.x >> 5;
    #pragma unroll
    for (int r = 0; r < 32; r += 8) {
        int c = cb + ty + r;
        int j = jb + tx;
        t[ty + r][tx] = (j < NJ) ? cw[(size_t)c * NJ + j] : 0.f;
    }
    __syncthreads();
    #pragma unroll
    for (int r = 0; r < 32; r += 8) {
        int j = jb + ty + r;
        int c = cb + tx;
        float v = t[tx][ty + r];
        split_store(&Bt[(size_t)j * (2 * C) + c], &Bt[(size_t)j * (2 * C) + C + c], v);
    }
}

// ---------------- Layer 0 producer -> A0 bf16 hi|lo ----------------
__global__ void __launch_bounds__(128) prep0_kernel(
    const float* __restrict__ inp, const float* __restrict__ wq,
    const float* __restrict__ wk, const float* __restrict__ wv,
    __nv_bfloat16* __restrict__ A0)
{
    __shared__ float u[F0], w[F0], v[F0], Sinv[F0];
    __shared__ float E[C0];
    int bk = blockIdx.x;
    int b = bk >> 5, k = bk & 31;
    int tid = threadIdx.x;

    if (tid < F0) {
        float x = inp[(size_t)(b * F0 + tid) * KDIM + k];
        u[tid] = x * wk[tid * KDIM + k];
        w[tid] = x * wv[tid * KDIM + k];
        v[tid] = x * wq[tid * KDIM + k];
    }
    __syncthreads();
    for (int idx = tid; idx < C0; idx += 128) {
        int f = idx / 40, g = idx - f * 40;
        E[idx] = __expf(u[f] * v[g]);
    }
    __syncthreads();
    if (tid < F0) {
        float s = 0.f;
        #pragma unroll
        for (int f = 0; f < F0; f++) s += E[f * 40 + tid];
        Sinv[tid] = 1.0f / s;
    }
    __syncthreads();
    __nv_bfloat16* rowp = A0 + (size_t)bk * (2 * C0);
    for (int idx = tid; idx < C0; idx += 128) {
        int f = idx / 40, g = idx - f * 40;
        float val = w[f] * E[idx] * Sinv[g];
        split_store(&rowp[idx], &rowp[C0 + idx], val);
    }
}

// ---------------- Layer 1 producer: column-owned, prefetched, chain-split ----
// block = (b, kg) : 512 blocks x 256 threads. Thread g (< 200) owns output
// column g; v for all KG k-slots prefetched; exp via bare ex2 (u pre-scaled
// by log2e at staging); softmax sum in 4 partial accumulators.
__global__ void __launch_bounds__(256) prep1_kernel(
    const float* __restrict__ inp, const float* __restrict__ out0,
    const float* __restrict__ wq, const float* __restrict__ wk,
    const float* __restrict__ wv, __nv_bfloat16* __restrict__ Xp)
{
    __shared__ float u2[KG][F0], w[KG][F0];   // u2 = u * log2(e)
    const int blk = blockIdx.x;       // 512 = b*2 + kg
    const int kg = blk & 1;
    const int b = blk >> 1;
    const int tid = threadIdx.x;

    for (int i = tid; i < KG * F0; i += 256) {
        int kk = i / F0, f = i - kk * F0;
        int k = kg * KG + kk;
        float x = inp[(size_t)(b * F0 + f) * KDIM + k];
        u2[kk][f] = x * wk[f * KDIM + k] * 1.44269504088896f;
        w[kk][f] = x * wv[f * KDIM + k];
    }
    __syncthreads();

    if (tid >= NJ) return;            // no further barriers: safe
    const int g = tid;

    // prefetch wq row (contiguous 16 floats) and out0 column values
    float wqv[KG];
    {
        const float4* wp = reinterpret_cast<const float4*>(wq + g * KDIM + kg * KG);
        #pragma unroll
        for (int q = 0; q < KG / 4; q++) {
            float4 t = wp[q];
            wqv[q * 4 + 0] = t.x; wqv[q * 4 + 1] = t.y;
            wqv[q * 4 + 2] = t.z; wqv[q * 4 + 3] = t.w;
        }
    }
    float v[KG];
    #pragma unroll
    for (int kk = 0; kk < KG; kk++) {
        int k = kg * KG + kk;
        v[kk] = out0[(size_t)(b * KDIM + k) * NJ + g];
    }
    #pragma unroll
    for (int kk = 0; kk < KG; kk++) v[kk] *= wqv[kk];

    float acc[F0];
    #pragma unroll
    for (int f = 0; f < F0; f++) acc[f] = 0.f;

    for (int kk = 0; kk < KG; kk++) {
        float vk = v[kk];
        float e[F0];
        float s0 = 0.f, s1 = 0.f, s2 = 0.f, s3 = 0.f;
        #pragma unroll
        for (int f = 0; f < F0; f += 4) {
            e[f + 0] = ex2(u2[kk][f + 0] * vk);
            e[f + 1] = ex2(u2[kk][f + 1] * vk);
            e[f + 2] = ex2(u2[kk][f + 2] * vk);
            e[f + 3] = ex2(u2[kk][f + 3] * vk);
            s0 += e[f + 0]; s1 += e[f + 1]; s2 += e[f + 2]; s3 += e[f + 3];
        }
        float sinv = 1.0f / ((s0 + s1) + (s2 + s3));
        #pragma unroll
        for (int f = 0; f < F0; f++)
            acc[f] += w[kk][f] * e[f] * sinv;
    }

    __nv_bfloat16* rowp = Xp + (size_t)blk * (2 * C1);
    #pragma unroll
    for (int f = 0; f < F0; f++) {
        int c = f * NJ + g;
        split_store(&rowp[c], &rowp[C1 + c], acc[f]);
    }
}

// ---------------- mma.sync bf16x3 GEMM body, compile-time NV specialization ----
template<int NV>
__device__ __forceinline__ void gemm_body(
    const __nv_bfloat16* __restrict__ A,
    const __nv_bfloat16* __restrict__ B,
    float* __restrict__ P, size_t sliceStride,
    int K, int cpz, int nc, int fold, char* sm)
{
    constexpr int n0 = (NV == 128) ? 0 : 128;
    constexpr int brows = (NV >= 128) ? 128 : ((NV + 15) & ~15);   // 128 or 80
    const int tid = threadIdx.x;
    const int lane = tid & 31;
    const int wid = tid >> 5;
    const int wm0 = (wid & 3) * 32;
    const int wn0 = (wid >> 2) * 64;
    const int m0 = blockIdx.x * 128;
    const int cpk = K / 64;
    const int lda = 2 * K;
    const int c0 = blockIdx.z * cpz;
    int c1 = c0 + cpz; if (c1 > nc) c1 = nc;

    const uint32_t sb = smem_u32(sm);
    float* Pz = P + (size_t)blockIdx.z * sliceStride;

    float acc[2][8][4];
    #pragma unroll
    for (int i = 0; i < 2; i++)
        #pragma unroll
        for (int j = 0; j < 8; j++)
            #pragma unroll
            for (int l = 0; l < 4; l++) acc[i][j][l] = 0.f;

    auto gissue = [&](int c, int st) {
        int region = c / cpk;
        int within = c - region * cpk;
        int acol = (region == 1 ? K : 0) + within * 64;
        int bcol = (region == 2 ? K : 0) + within * 64;
        uint32_t abase = sb + st * 32768;
        uint32_t bbase = abase + 16384;
        #pragma unroll
        for (int i = 0; i < 4; i++) {
            int idx = tid + 256 * i;
            int row = idx >> 3, q = idx & 7;
            cp16(abase + (row * 8 + (q ^ (row & 7))) * 16,
                 A + (size_t)(m0 + row) * lda + acol + q * 8);
        }
        #pragma unroll
        for (int i = 0; i < 4; i++) {
            int idx = tid + 256 * i;
            int row = idx >> 3, q = idx & 7;
            if (row < brows)     // compile-time bound
                cp16(bbase + (row * 8 + (q ^ (row & 7))) * 16,
                     B + (size_t)(n0 + row) * lda + bcol + q * 8);
        }
        cp_commit();
    };

    if (c0 < c1) gissue(c0, 0); else cp_commit();
    if (c0 + 1 < c1) gissue(c0 + 1, 1); else cp_commit();

    const int t3 = lane >> 3;
    const int r8 = lane & 7;
    const bool fullwarp = (NV >= 128) || (wn0 == 0);

    for (int c = c0; c < c1; c++) {
        int rel = c - c0;
        int st = rel % 3;
        cp_wait1();
        __syncthreads();
        if (c + 2 < c1) gissue(c + 2, (rel + 2) % 3);
        uint32_t ab = sb + st * 32768;
        uint32_t bb = ab + 16384;
        #pragma unroll
        for (int ks = 0; ks < 4; ks++) {
            int kc = ks * 2;
            uint32_t afr[2][4], bfr[4][4];
            #pragma unroll
            for (int mt = 0; mt < 2; mt++) {
                int m = wm0 + mt * 16 + (t3 & 1) * 8 + r8;
                int q = kc + (t3 >> 1);
                ldm_x4(afr[mt], ab + (m * 8 + (q ^ (m & 7))) * 16);
            }
            if (fullwarp) {
                #pragma unroll
                for (int np = 0; np < 4; np++) {
                    int n = wn0 + np * 16 + (t3 >> 1) * 8 + r8;
                    int q = kc + (t3 & 1);
                    ldm_x4(bfr[np], bb + (n * 8 + (q ^ (n & 7))) * 16);
                }
                #pragma unroll
                for (int mt = 0; mt < 2; mt++)
                    #pragma unroll
                    for (int nt = 0; nt < 8; nt++)
                        mma_bf16(acc[mt][nt], afr[mt],
                                 bfr[nt >> 1][(nt & 1) * 2], bfr[nt >> 1][(nt & 1) * 2 + 1]);
            } else {
                int n = wn0 + (t3 >> 1) * 8 + r8;
                int q = kc + (t3 & 1);
                ldm_x4(bfr[0], bb + (n * 8 + (q ^ (n & 7))) * 16);
                #pragma unroll
                for (int mt = 0; mt < 2; mt++)
                    mma_bf16(acc[mt][0], afr[mt], bfr[0][0], bfr[0][1]);
            }
        }
    }

    // epilogue: plain vectorized stores into this z-slice
    const int g = lane >> 2, t = lane & 3;
    if (!fold) {
        #pragma unroll
        for (int mt = 0; mt < 2; mt++) {
            #pragma unroll
            for (int nt = 0; nt < 8; nt++) {
                int row = m0 + wm0 + mt * 16 + g;
                int col = n0 + wn0 + nt * 8 + t * 2;
                if (col < NJ) {
                    *reinterpret_cast<float2*>(&Pz[(size_t)row * NJ + col]) =
                        make_float2(acc[mt][nt][0], acc[mt][nt][1]);
                    *reinterpret_cast<float2*>(&Pz[(size_t)(row + 8) * NJ + col]) =
                        make_float2(acc[mt][nt][2], acc[mt][nt][3]);
                }
            }
        }
    } else {
        #pragma unroll
        for (int mt = 0; mt < 2; mt++) {
            #pragma unroll
            for (int nt = 0; nt < 8; nt++) {
                float v0 = acc[mt][nt][0] + __shfl_xor_sync(0xFFFFFFFFu, acc[mt][nt][0], 4);
                float v1 = acc[mt][nt][1] + __shfl_xor_sync(0xFFFFFFFFu, acc[mt][nt][1], 4);
                float v2 = acc[mt][nt][2] + __shfl_xor_sync(0xFFFFFFFFu, acc[mt][nt][2], 4);
                float v3 = acc[mt][nt][3] + __shfl_xor_sync(0xFFFFFFFFu, acc[mt][nt][3], 4);
                int row = m0 + wm0 + mt * 16 + g;
                int col = n0 + wn0 + nt * 8 + t * 2;
                if ((g & 1) == 0 && col < NJ) {
                    int or0 = row >> 1;
                    int or1 = (row + 8) >> 1;
                    *reinterpret_cast<float2*>(&Pz[(size_t)or0 * NJ + col]) = make_float2(v0, v1);
                    *reinterpret_cast<float2*>(&Pz[(size_t)or1 * NJ + col]) = make_float2(v2, v3);
                }
            }
        }
    }
}

__global__ void __launch_bounds__(256, 2) mma_gemm_kernel(
    const __nv_bfloat16* __restrict__ A,
    const __nv_bfloat16* __restrict__ B,
    float* __restrict__ P, size_t sliceStride,
    int K, int cpz, int nc, int fold)
{
    extern __shared__ char sm[];       // 3 stages x (A 16KB + B 16KB) = 96KB
    if (blockIdx.y == 0)
        gemm_body<128>(A, B, P, sliceStride, K, cpz, nc, fold, sm);
    else
        gemm_body<72>(A, B, P, sliceStride, K, cpz, nc, fold, sm);
}

// ---------------- sum Z0 partial slices -> O0 (float4) ----------------
__global__ void sum4_kernel(const float* __restrict__ P, float* __restrict__ O, int n4) {
    int i = blockIdx.x * 256 + threadIdx.x;
    if (i >= n4) return;
    const float4* p = reinterpret_cast<const float4*>(P);
    float4 a = p[i];
    float4 b = p[i + n4];
    float4 c = p[i + 2 * n4];
    float4 d = p[i + 3 * n4];
    reinterpret_cast<float4*>(O)[i] =
        make_float4(a.x + b.x + c.x + d.x, a.y + b.y + c.y + d.y,
                    a.z + b.z + c.z + d.z, a.w + b.w + c.w + d.w);
}

// ---------------- Final reduce: [B, 400] ----------------
__global__ void reduce_kernel(const float* __restrict__ out0,
                              const float* __restrict__ P1,
                              float* __restrict__ res)
{
    int i = blockIdx.x * 256 + threadIdx.x;
    if (i >= BATCH * 2 * NJ) return;
    int b = i / (2 * NJ), j = i % (2 * NJ);
    if (j < NJ) {
        float s = 0.f;
        #pragma unroll
        for (int k = 0; k < KDIM; k++)
            s += out0[(size_t)(b * KDIM + k) * NJ + j];
        res[i] = s;
    } else {
        float s = 0.f;
        #pragma unroll
        for (int z = 0; z < Z1; z++)
            s += P1[(size_t)z * BATCH * NJ + (size_t)b * NJ + (j - NJ)];
        res[i] = s;
    }
}

extern "C" void kernel_launch(void* const* d_in, const int* in_sizes, int n_in,
                              void* d_out, int out_size)
{
    const float* inp = (const float*)d_in[0];
    const float* wq0 = (const float*)d_in[1];
    const float* wk0 = (const float*)d_in[2];
    const float* wv0 = (const float*)d_in[3];
    const float* cw0 = (const float*)d_in[4];
    const float* wq1 = (const float*)d_in[5];
    const float* wk1 = (const float*)d_in[6];
    const float* wv1 = (const float*)d_in[7];
    const float* cw1 = (const float*)d_in[8];
    float* out = (float*)d_out;

    __nv_bfloat16 *A0, *Xp, *B0, *B1;
    float *P0, *P1, *O0;
    cudaGetSymbolAddress((void**)&A0, g_A0);
    cudaGetSymbolAddress((void**)&Xp, g_Xp);
    cudaGetSymbolAddress((void**)&B0, g_B0);
    cudaGetSymbolAddress((void**)&B1, g_B1);
    cudaGetSymbolAddress((void**)&P0, g_P0);
    cudaGetSymbolAddress((void**)&P1, g_P1);
    cudaGetSymbolAddress((void**)&O0, g_O0);

    cudaFuncSetAttribute(mma_gemm_kernel, cudaFuncAttributeMaxDynamicSharedMemorySize, 98304);

    // weight transpose + bf16 split
    bprep_kernel<<<dim3(C0 / 32, 8), 256>>>(cw0, B0, C0);
    bprep_kernel<<<dim3(C1 / 32, 8), 256>>>(cw1, B1, C1);

    // layer 0
    prep0_kernel<<<M0, 128>>>(inp, wq0, wk0, wv0, A0);
    // M=8192 (64 tiles), 2 n-tiles (compile-time specialized), nc=75, Z0=4 (cpz=19)
    mma_gemm_kernel<<<dim3(64, 2, Z0), 256, 98304>>>(A0, B0, P0, (size_t)M0 * NJ, C0, 19, 75, 0);
    sum4_kernel<<<(M0 * NJ / 4 + 255) / 256, 256>>>(P0, O0, M0 * NJ / 4);

    // layer 1 (k-presummed, column-owned producer)
    prep1_kernel<<<M1, 256>>>(inp, O0, wq1, wk1, wv1, Xp);
    // M=512 (4 tiles), nc=375 chunks, Z1=37 (cpz=11) -> 296 CTAs (1 full wave @ 2/SM)
    mma_gemm_kernel<<<dim3(4, 2, Z1), 256, 98304>>>(Xp, B1, P1, (size_t)BATCH * NJ, C1, 11, 375, 1);

    reduce_kernel<<<(BATCH * 2 * NJ + 255) / 256, 256>>>(O0, P1, out);
}

// round 10
// speedup vs baseline: 1.6994x; 1.0907x over previous
#include <cuda_runtime.h>
#include <cuda_bf16.h>
#include <cstdint>
#include <cstddef>

#define BATCH 256
#define F0    40
#define KDIM  32
#define NJ    200
#define C0    1600
#define C1    8000
#define M0    8192
#define KG    16
#define M1    512
#define Z0    4      // split-K slices layer 0
#define Z1    37     // split-K slices layer 1

// ---- scratch (static __device__, per harness rules) ----
__device__ __align__(16) __nv_bfloat16 g_A0[(size_t)M0 * 2 * C0];   // [8192, 3200]  hi|lo
__device__ __align__(16) __nv_bfloat16 g_Xp[(size_t)M1 * 2 * C1];   // [512, 16000]  hi|lo
__device__ __align__(16) __nv_bfloat16 g_B0[(size_t)256 * 2 * C0];  // [256, 3200]   hi|lo
__device__ __align__(16) __nv_bfloat16 g_B1[(size_t)256 * 2 * C1];  // [256, 16000]
__device__ __align__(16) float g_P0[(size_t)Z0 * M0 * NJ];          // gemm0 partials
__device__ __align__(16) float g_P1[(size_t)Z1 * BATCH * NJ];       // gemm1 partials
__device__ __align__(16) float g_O0[(size_t)M0 * NJ];               // summed out0

// ================= helpers =================
__device__ __forceinline__ uint32_t smem_u32(const void* p) {
    uint32_t a;
    asm("{ .reg .u64 t; cvta.to.shared.u64 t, %1; cvt.u32.u64 %0, t; }" : "=r"(a) : "l"(p));
    return a;
}

__device__ __forceinline__ float ex2(float x) {
    float y;
    asm("ex2.approx.ftz.f32 %0, %1;" : "=f"(y) : "f"(x));
    return y;
}

__device__ __forceinline__ void ldm_x4(uint32_t* r, uint32_t addr) {
    asm volatile("ldmatrix.sync.aligned.m8n8.x4.shared.b16 {%0,%1,%2,%3}, [%4];"
        : "=r"(r[0]), "=r"(r[1]), "=r"(r[2]), "=r"(r[3]) : "r"(addr));
}

__device__ __forceinline__ void mma_bf16(float* d, const uint32_t* a, uint32_t b0, uint32_t b1) {
    asm volatile("mma.sync.aligned.m16n8k16.row.col.f32.bf16.bf16.f32 "
        "{%0,%1,%2,%3}, {%4,%5,%6,%7}, {%8,%9}, {%0,%1,%2,%3};"
        : "+f"(d[0]), "+f"(d[1]), "+f"(d[2]), "+f"(d[3])
        : "r"(a[0]), "r"(a[1]), "r"(a[2]), "r"(a[3]), "r"(b0), "r"(b1));
}

__device__ __forceinline__ void cp16(uint32_t saddr, const void* gaddr) {
    asm volatile("cp.async.cg.shared.global [%0], [%1], 16;" :: "r"(saddr), "l"(gaddr));
}
__device__ __forceinline__ void cp_commit() { asm volatile("cp.async.commit_group;" ::: "memory"); }
__device__ __forceinline__ void cp_wait1()  { asm volatile("cp.async.wait_group 1;" ::: "memory"); }

__device__ __forceinline__ void split_store(__nv_bfloat16* hi_p, __nv_bfloat16* lo_p, float v) {
    __nv_bfloat16 h = __float2bfloat16(v);
    *hi_p = h;
    *lo_p = __float2bfloat16(v - __bfloat162float(h));
}

// ================= weight prep (both weights, one launch, coalesced) ==========
// 64c x 32j tiles. Reads 128B-coalesced rows of cw; writes 128B runs of bf16.
__global__ void __launch_bounds__(256) bprep2_kernel(
    const float* __restrict__ cw0, const float* __restrict__ cw1,
    __nv_bfloat16* __restrict__ B0w, __nv_bfloat16* __restrict__ B1w)
{
    __shared__ float t[64][33];
    const int bx = blockIdx.x;
    const float* cw; __nv_bfloat16* Bt; int C, cb;
    if (bx < C0 / 64) { cw = cw0; Bt = B0w; C = C0; cb = bx * 64; }
    else              { cw = cw1; Bt = B1w; C = C1; cb = (bx - C0 / 64) * 64; }
    const int jb = blockIdx.y * 32;

    int tx = threadIdx.x & 31, ty = threadIdx.x >> 5;   // j, c-sub
    #pragma unroll
    for (int r = 0; r < 64; r += 8) {
        int c = cb + ty + r;
        int j = jb + tx;
        t[ty + r][tx] = (j < NJ) ? cw[(size_t)c * NJ + j] : 0.f;
    }
    __syncthreads();
    int cx = threadIdx.x & 63, jy = threadIdx.x >> 6;   // c, j-sub
    #pragma unroll
    for (int r = 0; r < 32; r += 4) {
        int j = jb + jy + r;
        float v = t[cx][jy + r];
        split_store(&Bt[(size_t)j * (2 * C) + cb + cx],
                    &Bt[(size_t)j * (2 * C) + C + cb + cx], v);
    }
}

// ---------------- Layer 0 producer: column-owned, single barrier ----------------
// block = b (256 blocks x 256 threads). Cells (k,g): 32*40 = 1280; 5 per thread.
__global__ void __launch_bounds__(256) prep0_kernel(
    const float* __restrict__ inp, const float* __restrict__ wq,
    const float* __restrict__ wk, const float* __restrict__ wv,
    __nv_bfloat16* __restrict__ A0)
{
    __shared__ float u2[KDIM][F0], w[KDIM][F0], v[KDIM][F0];
    const int b = blockIdx.x;
    const int tid = threadIdx.x;

    for (int i = tid; i < KDIM * F0; i += 256) {
        int f = i >> 5, k = i & 31;          // k minor: coalesced
        float x = inp[(size_t)(b * F0 + f) * KDIM + k];
        u2[k][f] = x * wk[f * KDIM + k] * 1.44269504088896f;
        w[k][f]  = x * wv[f * KDIM + k];
        v[k][f]  = x * wq[f * KDIM + k];
    }
    __syncthreads();

    #pragma unroll
    for (int i = 0; i < 5; i++) {
        int idx = tid + 256 * i;             // 0..1279
        int k = idx / 40;
        int g = idx - k * 40;
        float vg = v[k][g];
        float e[F0];
        float s0 = 0.f, s1 = 0.f, s2 = 0.f, s3 = 0.f;
        #pragma unroll
        for (int f = 0; f < F0; f += 4) {
            e[f + 0] = ex2(u2[k][f + 0] * vg);
            e[f + 1] = ex2(u2[k][f + 1] * vg);
            e[f + 2] = ex2(u2[k][f + 2] * vg);
            e[f + 3] = ex2(u2[k][f + 3] * vg);
            s0 += e[f + 0]; s1 += e[f + 1]; s2 += e[f + 2]; s3 += e[f + 3];
        }
        float sinv = 1.0f / ((s0 + s1) + (s2 + s3));
        __nv_bfloat16* rowp = A0 + (size_t)(b * KDIM + k) * (2 * C0);
        #pragma unroll
        for (int f = 0; f < F0; f++) {
            float val = w[k][f] * e[f] * sinv;
            split_store(&rowp[f * 40 + g], &rowp[C0 + f * 40 + g], val);
        }
    }
}

// ---------------- Layer 1 producer: column-owned, prefetched, chain-split ----
__global__ void __launch_bounds__(256) prep1_kernel(
    const float* __restrict__ inp, const float* __restrict__ out0,
    const float* __restrict__ wq, const float* __restrict__ wk,
    const float* __restrict__ wv, __nv_bfloat16* __restrict__ Xp)
{
    __shared__ float u2[KG][F0], w[KG][F0];   // u2 = u * log2(e)
    const int blk = blockIdx.x;       // 512 = b*2 + kg
    const int kg = blk & 1;
    const int b = blk >> 1;
    const int tid = threadIdx.x;

    for (int i = tid; i < KG * F0; i += 256) {
        int kk = i / F0, f = i - kk * F0;
        int k = kg * KG + kk;
        float x = inp[(size_t)(b * F0 + f) * KDIM + k];
        u2[kk][f] = x * wk[f * KDIM + k] * 1.44269504088896f;
        w[kk][f] = x * wv[f * KDIM + k];
    }
    __syncthreads();

    if (tid >= NJ) return;            // no further barriers: safe
    const int g = tid;

    float wqv[KG];
    {
        const float4* wp = reinterpret_cast<const float4*>(wq + g * KDIM + kg * KG);
        #pragma unroll
        for (int q = 0; q < KG / 4; q++) {
            float4 t = wp[q];
            wqv[q * 4 + 0] = t.x; wqv[q * 4 + 1] = t.y;
            wqv[q * 4 + 2] = t.z; wqv[q * 4 + 3] = t.w;
        }
    }
    float v[KG];
    #pragma unroll
    for (int kk = 0; kk < KG; kk++) {
        int k = kg * KG + kk;
        v[kk] = out0[(size_t)(b * KDIM + k) * NJ + g];
    }
    #pragma unroll
    for (int kk = 0; kk < KG; kk++) v[kk] *= wqv[kk];

    float acc[F0];
    #pragma unroll
    for (int f = 0; f < F0; f++) acc[f] = 0.f;

    for (int kk = 0; kk < KG; kk++) {
        float vk = v[kk];
        float e[F0];
        float s0 = 0.f, s1 = 0.f, s2 = 0.f, s3 = 0.f;
        #pragma unroll
        for (int f = 0; f < F0; f += 4) {
            e[f + 0] = ex2(u2[kk][f + 0] * vk);
            e[f + 1] = ex2(u2[kk][f + 1] * vk);
            e[f + 2] = ex2(u2[kk][f + 2] * vk);
            e[f + 3] = ex2(u2[kk][f + 3] * vk);
            s0 += e[f + 0]; s1 += e[f + 1]; s2 += e[f + 2]; s3 += e[f + 3];
        }
        float sinv = 1.0f / ((s0 + s1) + (s2 + s3));
        #pragma unroll
        for (int f = 0; f < F0; f++)
            acc[f] += w[kk][f] * e[f] * sinv;
    }

    __nv_bfloat16* rowp = Xp + (size_t)blk * (2 * C1);
    #pragma unroll
    for (int f = 0; f < F0; f++) {
        int c = f * NJ + g;
        split_store(&rowp[c], &rowp[C1 + c], acc[f]);
    }
}

// ---------------- mma.sync bf16x3 GEMM body, compile-time NV specialization ----
template<int NV>
__device__ __forceinline__ void gemm_body(
    const __nv_bfloat16* __restrict__ A,
    const __nv_bfloat16* __restrict__ B,
    float* __restrict__ P, size_t sliceStride,
    int K, int cpz, int nc, int fold, char* sm)
{
    constexpr int n0 = (NV == 128) ? 0 : 128;
    constexpr int brows = (NV >= 128) ? 128 : ((NV + 15) & ~15);   // 128 or 80
    const int tid = threadIdx.x;
    const int lane = tid & 31;
    const int wid = tid >> 5;
    const int wm0 = (wid & 3) * 32;
    const int wn0 = (wid >> 2) * 64;
    const int m0 = blockIdx.x * 128;
    const int cpk = K / 64;
    const int lda = 2 * K;
    const int c0 = blockIdx.z * cpz;
    int c1 = c0 + cpz; if (c1 > nc) c1 = nc;

    const uint32_t sb = smem_u32(sm);
    float* Pz = P + (size_t)blockIdx.z * sliceStride;

    float acc[2][8][4];
    #pragma unroll
    for (int i = 0; i < 2; i++)
        #pragma unroll
        for (int j = 0; j < 8; j++)
            #pragma unroll
            for (int l = 0; l < 4; l++) acc[i][j][l] = 0.f;

    auto gissue = [&](int c, int st) {
        int region = c / cpk;
        int within = c - region * cpk;
        int acol = (region == 1 ? K : 0) + within * 64;
        int bcol = (region == 2 ? K : 0) + within * 64;
        uint32_t abase = sb + st * 32768;
        uint32_t bbase = abase + 16384;
        #pragma unroll
        for (int i = 0; i < 4; i++) {
            int idx = tid + 256 * i;
            int row = idx >> 3, q = idx & 7;
            cp16(abase + (row * 8 + (q ^ (row & 7))) * 16,
                 A + (size_t)(m0 + row) * lda + acol + q * 8);
        }
        #pragma unroll
        for (int i = 0; i < 4; i++) {
            int idx = tid + 256 * i;
            int row = idx >> 3, q = idx & 7;
            if (row < brows)     // compile-time bound
                cp16(bbase + (row * 8 + (q ^ (row & 7))) * 16,
                     B + (size_t)(n0 + row) * lda + bcol + q * 8);
        }
        cp_commit();
    };

    if (c0 < c1) gissue(c0, 0); else cp_commit();
    if (c0 + 1 < c1) gissue(c0 + 1, 1); else cp_commit();

    const int t3 = lane >> 3;
    const int r8 = lane & 7;
    const bool fullwarp = (NV >= 128) || (wn0 == 0);

    for (int c = c0; c < c1; c++) {
        int rel = c - c0;
        int st = rel % 3;
        cp_wait1();
        __syncthreads();
        if (c + 2 < c1) gissue(c + 2, (rel + 2) % 3);
        uint32_t ab = sb + st * 32768;
        uint32_t bb = ab + 16384;
        #pragma unroll
        for (int ks = 0; ks < 4; ks++) {
            int kc = ks * 2;
            uint32_t afr[2][4], bfr[4][4];
            #pragma unroll
            for (int mt = 0; mt < 2; mt++) {
                int m = wm0 + mt * 16 + (t3 & 1) * 8 + r8;
                int q = kc + (t3 >> 1);
                ldm_x4(afr[mt], ab + (m * 8 + (q ^ (m & 7))) * 16);
            }
            if (fullwarp) {
                #pragma unroll
                for (int np = 0; np < 4; np++) {
                    int n = wn0 + np * 16 + (t3 >> 1) * 8 + r8;
                    int q = kc + (t3 & 1);
                    ldm_x4(bfr[np], bb + (n * 8 + (q ^ (n & 7))) * 16);
                }
                #pragma unroll
                for (int mt = 0; mt < 2; mt++)
                    #pragma unroll
                    for (int nt = 0; nt < 8; nt++)
                        mma_bf16(acc[mt][nt], afr[mt],
                                 bfr[nt >> 1][(nt & 1) * 2], bfr[nt >> 1][(nt & 1) * 2 + 1]);
            } else {
                int n = wn0 + (t3 >> 1) * 8 + r8;
                int q = kc + (t3 & 1);
                ldm_x4(bfr[0], bb + (n * 8 + (q ^ (n & 7))) * 16);
                #pragma unroll
                for (int mt = 0; mt < 2; mt++)
                    mma_bf16(acc[mt][0], afr[mt], bfr[0][0], bfr[0][1]);
            }
        }
    }

    // epilogue: plain vectorized stores into this z-slice
    const int g = lane >> 2, t = lane & 3;
    if (!fold) {
        #pragma unroll
        for (int mt = 0; mt < 2; mt++) {
            #pragma unroll
            for (int nt = 0; nt < 8; nt++) {
                int row = m0 + wm0 + mt * 16 + g;
                int col = n0 + wn0 + nt * 8 + t * 2;
                if (col < NJ) {
                    *reinterpret_cast<float2*>(&Pz[(size_t)row * NJ + col]) =
                        make_float2(acc[mt][nt][0], acc[mt][nt][1]);
                    *reinterpret_cast<float2*>(&Pz[(size_t)(row + 8) * NJ + col]) =
                        make_float2(acc[mt][nt][2], acc[mt][nt][3]);
                }
            }
        }
    } else {
        #pragma unroll
        for (int mt = 0; mt < 2; mt++) {
            #pragma unroll
            for (int nt = 0; nt < 8; nt++) {
                float v0 = acc[mt][nt][0] + __shfl_xor_sync(0xFFFFFFFFu, acc[mt][nt][0], 4);
                float v1 = acc[mt][nt][1] + __shfl_xor_sync(0xFFFFFFFFu, acc[mt][nt][1], 4);
                float v2 = acc[mt][nt][2] + __shfl_xor_sync(0xFFFFFFFFu, acc[mt][nt][2], 4);
                float v3 = acc[mt][nt][3] + __shfl_xor_sync(0xFFFFFFFFu, acc[mt][nt][3], 4);
                int row = m0 + wm0 + mt * 16 + g;
                int col = n0 + wn0 + nt * 8 + t * 2;
                if ((g & 1) == 0 && col < NJ) {
                    int or0 = row >> 1;
                    int or1 = (row + 8) >> 1;
                    *reinterpret_cast<float2*>(&Pz[(size_t)or0 * NJ + col]) = make_float2(v0, v1);
                    *reinterpret_cast<float2*>(&Pz[(size_t)or1 * NJ + col]) = make_float2(v2, v3);
                }
            }
        }
    }
}

__global__ void __launch_bounds__(256, 2) mma_gemm_kernel(
    const __nv_bfloat16* __restrict__ A,
    const __nv_bfloat16* __restrict__ B,
    float* __restrict__ P, size_t sliceStride,
    int K, int cpz, int nc, int fold)
{
    extern __shared__ char sm[];       // 3 stages x (A 16KB + B 16KB) = 96KB
    if (blockIdx.y == 0)
        gemm_body<128>(A, B, P, sliceStride, K, cpz, nc, fold, sm);
    else
        gemm_body<72>(A, B, P, sliceStride, K, cpz, nc, fold, sm);
}

// ---------------- sum Z0 partial slices -> O0 (float4) ----------------
__global__ void sum4_kernel(const float* __restrict__ P, float* __restrict__ O, int n4) {
    int i = blockIdx.x * 256 + threadIdx.x;
    if (i >= n4) return;
    const float4* p = reinterpret_cast<const float4*>(P);
    float4 a = p[i];
    float4 b = p[i + n4];
    float4 c = p[i + 2 * n4];
    float4 d = p[i + 3 * n4];
    reinterpret_cast<float4*>(O)[i] =
        make_float4(a.x + b.x + c.x + d.x, a.y + b.y + c.y + d.y,
                    a.z + b.z + c.z + d.z, a.w + b.w + c.w + d.w);
}

// ---------------- Final reduce: [B, 400] ----------------
__global__ void reduce_kernel(const float* __restrict__ out0,
                              const float* __restrict__ P1,
                              float* __restrict__ res)
{
    int i = blockIdx.x * 256 + threadIdx.x;
    if (i >= BATCH * 2 * NJ) return;
    int b = i / (2 * NJ), j = i % (2 * NJ);
    if (j < NJ) {
        float s = 0.f;
        #pragma unroll
        for (int k = 0; k < KDIM; k++)
            s += out0[(size_t)(b * KDIM + k) * NJ + j];
        res[i] = s;
    } else {
        float s = 0.f;
        #pragma unroll
        for (int z = 0; z < Z1; z++)
            s += P1[(size_t)z * BATCH * NJ + (size_t)b * NJ + (j - NJ)];
        res[i] = s;
    }
}

extern "C" void kernel_launch(void* const* d_in, const int* in_sizes, int n_in,
                              void* d_out, int out_size)
{
    const float* inp = (const float*)d_in[0];
    const float* wq0 = (const float*)d_in[1];
    const float* wk0 = (const float*)d_in[2];
    const float* wv0 = (const float*)d_in[3];
    const float* cw0 = (const float*)d_in[4];
    const float* wq1 = (const float*)d_in[5];
    const float* wk1 = (const float*)d_in[6];
    const float* wv1 = (const float*)d_in[7];
    const float* cw1 = (const float*)d_in[8];
    float* out = (float*)d_out;

    __nv_bfloat16 *A0, *Xp, *B0, *B1;
    float *P0, *P1, *O0;
    cudaGetSymbolAddress((void**)&A0, g_A0);
    cudaGetSymbolAddress((void**)&Xp, g_Xp);
    cudaGetSymbolAddress((void**)&B0, g_B0);
    cudaGetSymbolAddress((void**)&B1, g_B1);
    cudaGetSymbolAddress((void**)&P0, g_P0);
    cudaGetSymbolAddress((void**)&P1, g_P1);
    cudaGetSymbolAddress((void**)&O0, g_O0);

    cudaFuncSetAttribute(mma_gemm_kernel, cudaFuncAttributeMaxDynamicSharedMemorySize, 98304);

    // both weight transposes + bf16 splits in ONE launch
    bprep2_kernel<<<dim3(C0 / 64 + C1 / 64, 8), 256>>>(cw0, cw1, B0, B1);

    // layer 0
    prep0_kernel<<<BATCH, 256>>>(inp, wq0, wk0, wv0, A0);
    // M=8192 (64 tiles), 2 n-tiles (compile-time specialized), nc=75, Z0=4 (cpz=19)
    mma_gemm_kernel<<<dim3(64, 2, Z0), 256, 98304>>>(A0, B0, P0, (size_t)M0 * NJ, C0, 19, 75, 0);
    sum4_kernel<<<(M0 * NJ / 4 + 255) / 256, 256>>>(P0, O0, M0 * NJ / 4);

    // layer 1 (k-presummed, column-owned producer)
    prep1_kernel<<<M1, 256>>>(inp, O0, wq1, wk1, wv1, Xp);
    // M=512 (4 tiles), nc=375 chunks, Z1=37 (cpz=11) -> 296 CTAs (1 full wave @ 2/SM)
    mma_gemm_kernel<<<dim3(4, 2, Z1), 256, 98304>>>(Xp, B1, P1, (size_t)BATCH * NJ, C1, 11, 375, 1);

    reduce_kernel<<<(BATCH * 2 * NJ + 255) / 256, 256>>>(O0, P1, out);
}

// round 11
// speedup vs baseline: 1.7275x; 1.0166x over previous
#include <cuda_runtime.h>
#include <cuda_bf16.h>
#include <cstdint>
#include <cstddef>

#define BATCH 256
#define F0    40
#define KDIM  32
#define NJ    200
#define C0    1600
#define C1    8000
#define M0    8192
#define KG    16
#define M1    512
#define Z0    4      // split-K slices layer 0
#define Z1    37     // split-K slices layer 1

// ---- scratch (static __device__, per harness rules) ----
__device__ __align__(16) __nv_bfloat16 g_A0[(size_t)M0 * 2 * C0];   // [8192, 3200]  hi|lo
__device__ __align__(16) __nv_bfloat16 g_Xp[(size_t)M1 * 2 * C1];   // [512, 16000]  hi|lo
__device__ __align__(16) __nv_bfloat16 g_B0[(size_t)256 * 2 * C0];  // [256, 3200]   hi|lo
__device__ __align__(16) __nv_bfloat16 g_B1[(size_t)256 * 2 * C1];  // [256, 16000]
__device__ __align__(16) float g_P0[(size_t)Z0 * M0 * NJ];          // gemm0 partials
__device__ __align__(16) float g_P1[(size_t)Z1 * BATCH * NJ];       // gemm1 partials
__device__ __align__(16) float g_O0[(size_t)M0 * NJ];               // summed out0

// ================= helpers =================
__device__ __forceinline__ uint32_t smem_u32(const void* p) {
    uint32_t a;
    asm("{ .reg .u64 t; cvta.to.shared.u64 t, %1; cvt.u32.u64 %0, t; }" : "=r"(a) : "l"(p));
    return a;
}

__device__ __forceinline__ float ex2(float x) {
    float y;
    asm("ex2.approx.ftz.f32 %0, %1;" : "=f"(y) : "f"(x));
    return y;
}

__device__ __forceinline__ void ldm_x4(uint32_t* r, uint32_t addr) {
    asm volatile("ldmatrix.sync.aligned.m8n8.x4.shared.b16 {%0,%1,%2,%3}, [%4];"
        : "=r"(r[0]), "=r"(r[1]), "=r"(r[2]), "=r"(r[3]) : "r"(addr));
}

__device__ __forceinline__ void mma_bf16(float* d, const uint32_t* a, uint32_t b0, uint32_t b1) {
    asm volatile("mma.sync.aligned.m16n8k16.row.col.f32.bf16.bf16.f32 "
        "{%0,%1,%2,%3}, {%4,%5,%6,%7}, {%8,%9}, {%0,%1,%2,%3};"
        : "+f"(d[0]), "+f"(d[1]), "+f"(d[2]), "+f"(d[3])
        : "r"(a[0]), "r"(a[1]), "r"(a[2]), "r"(a[3]), "r"(b0), "r"(b1));
}

__device__ __forceinline__ void cp16(uint32_t saddr, const void* gaddr) {
    asm volatile("cp.async.cg.shared.global [%0], [%1], 16;" :: "r"(saddr), "l"(gaddr));
}
__device__ __forceinline__ void cp_commit() { asm volatile("cp.async.commit_group;" ::: "memory"); }
__device__ __forceinline__ void cp_wait1()  { asm volatile("cp.async.wait_group 1;" ::: "memory"); }

__device__ __forceinline__ void split_store(__nv_bfloat16* hi_p, __nv_bfloat16* lo_p, float v) {
    __nv_bfloat16 h = __float2bfloat16(v);
    *hi_p = h;
    *lo_p = __float2bfloat16(v - __bfloat162float(h));
}

// ================= weight prep (both weights, one launch, coalesced) ==========
__global__ void __launch_bounds__(256) bprep2_kernel(
    const float* __restrict__ cw0, const float* __restrict__ cw1,
    __nv_bfloat16* __restrict__ B0w, __nv_bfloat16* __restrict__ B1w)
{
    __shared__ float t[64][33];
    const int bx = blockIdx.x;
    const float* cw; __nv_bfloat16* Bt; int C, cb;
    if (bx < C0 / 64) { cw = cw0; Bt = B0w; C = C0; cb = bx * 64; }
    else              { cw = cw1; Bt = B1w; C = C1; cb = (bx - C0 / 64) * 64; }
    const int jb = blockIdx.y * 32;

    int tx = threadIdx.x & 31, ty = threadIdx.x >> 5;   // j, c-sub
    #pragma unroll
    for (int r = 0; r < 64; r += 8) {
        int c = cb + ty + r;
        int j = jb + tx;
        t[ty + r][tx] = (j < NJ) ? cw[(size_t)c * NJ + j] : 0.f;
    }
    __syncthreads();
    int cx = threadIdx.x & 63, jy = threadIdx.x >> 6;   // c, j-sub
    #pragma unroll
    for (int r = 0; r < 32; r += 4) {
        int j = jb + jy + r;
        float v = t[cx][jy + r];
        split_store(&Bt[(size_t)j * (2 * C) + cb + cx],
                    &Bt[(size_t)j * (2 * C) + C + cb + cx], v);
    }
}

// ---------------- Layer 0 producer: column-owned, single barrier ----------------
__global__ void __launch_bounds__(256) prep0_kernel(
    const float* __restrict__ inp, const float* __restrict__ wq,
    const float* __restrict__ wk, const float* __restrict__ wv,
    __nv_bfloat16* __restrict__ A0)
{
    __shared__ float u2[KDIM][F0], w[KDIM][F0], v[KDIM][F0];
    const int b = blockIdx.x;
    const int tid = threadIdx.x;

    for (int i = tid; i < KDIM * F0; i += 256) {
        int f = i >> 5, k = i & 31;          // k minor: coalesced
        float x = inp[(size_t)(b * F0 + f) * KDIM + k];
        u2[k][f] = x * wk[f * KDIM + k] * 1.44269504088896f;
        w[k][f]  = x * wv[f * KDIM + k];
        v[k][f]  = x * wq[f * KDIM + k];
    }
    __syncthreads();

    #pragma unroll
    for (int i = 0; i < 5; i++) {
        int idx = tid + 256 * i;             // 0..1279
        int k = idx / 40;
        int g = idx - k * 40;
        float vg = v[k][g];
        float e[F0];
        float s0 = 0.f, s1 = 0.f, s2 = 0.f, s3 = 0.f;
        #pragma unroll
        for (int f = 0; f < F0; f += 4) {
            e[f + 0] = ex2(u2[k][f + 0] * vg);
            e[f + 1] = ex2(u2[k][f + 1] * vg);
            e[f + 2] = ex2(u2[k][f + 2] * vg);
            e[f + 3] = ex2(u2[k][f + 3] * vg);
            s0 += e[f + 0]; s1 += e[f + 1]; s2 += e[f + 2]; s3 += e[f + 3];
        }
        float sinv = 1.0f / ((s0 + s1) + (s2 + s3));
        __nv_bfloat16* rowp = A0 + (size_t)(b * KDIM + k) * (2 * C0);
        #pragma unroll
        for (int f = 0; f < F0; f++) {
            float val = w[k][f] * e[f] * sinv;
            split_store(&rowp[f * 40 + g], &rowp[C0 + f * 40 + g], val);
        }
    }
}

// ---------------- Layer 1 producer: column-owned, prefetched, chain-split ----
__global__ void __launch_bounds__(256) prep1_kernel(
    const float* __restrict__ inp, const float* __restrict__ out0,
    const float* __restrict__ wq, const float* __restrict__ wk,
    const float* __restrict__ wv, __nv_bfloat16* __restrict__ Xp)
{
    __shared__ float u2[KG][F0], w[KG][F0];   // u2 = u * log2(e)
    const int blk = blockIdx.x;       // 512 = b*2 + kg
    const int kg = blk & 1;
    const int b = blk >> 1;
    const int tid = threadIdx.x;

    for (int i = tid; i < KG * F0; i += 256) {
        int kk = i / F0, f = i - kk * F0;
        int k = kg * KG + kk;
        float x = inp[(size_t)(b * F0 + f) * KDIM + k];
        u2[kk][f] = x * wk[f * KDIM + k] * 1.44269504088896f;
        w[kk][f] = x * wv[f * KDIM + k];
    }
    __syncthreads();

    if (tid >= NJ) return;            // no further barriers: safe
    const int g = tid;

    float wqv[KG];
    {
        const float4* wp = reinterpret_cast<const float4*>(wq + g * KDIM + kg * KG);
        #pragma unroll
        for (int q = 0; q < KG / 4; q++) {
            float4 t = wp[q];
            wqv[q * 4 + 0] = t.x; wqv[q * 4 + 1] = t.y;
            wqv[q * 4 + 2] = t.z; wqv[q * 4 + 3] = t.w;
        }
    }
    float v[KG];
    #pragma unroll
    for (int kk = 0; kk < KG; kk++) {
        int k = kg * KG + kk;
        v[kk] = out0[(size_t)(b * KDIM + k) * NJ + g];
    }
    #pragma unroll
    for (int kk = 0; kk < KG; kk++) v[kk] *= wqv[kk];

    float acc[F0];
    #pragma unroll
    for (int f = 0; f < F0; f++) acc[f] = 0.f;

    for (int kk = 0; kk < KG; kk++) {
        float vk = v[kk];
        float e[F0];
        float s0 = 0.f, s1 = 0.f, s2 = 0.f, s3 = 0.f;
        #pragma unroll
        for (int f = 0; f < F0; f += 4) {
            e[f + 0] = ex2(u2[kk][f + 0] * vk);
            e[f + 1] = ex2(u2[kk][f + 1] * vk);
            e[f + 2] = ex2(u2[kk][f + 2] * vk);
            e[f + 3] = ex2(u2[kk][f + 3] * vk);
            s0 += e[f + 0]; s1 += e[f + 1]; s2 += e[f + 2]; s3 += e[f + 3];
        }
        float sinv = 1.0f / ((s0 + s1) + (s2 + s3));
        #pragma unroll
        for (int f = 0; f < F0; f++)
            acc[f] += w[kk][f] * e[f] * sinv;
    }

    __nv_bfloat16* rowp = Xp + (size_t)blk * (2 * C1);
    #pragma unroll
    for (int f = 0; f < F0; f++) {
        int c = f * NJ + g;
        split_store(&rowp[c], &rowp[C1 + c], acc[f]);
    }
}

// ---------------- mma.sync bf16x3 GEMM body, frag-pipelined inner loop ----------
template<int NV>
__device__ __forceinline__ void gemm_body(
    const __nv_bfloat16* __restrict__ A,
    const __nv_bfloat16* __restrict__ B,
    float* __restrict__ P, size_t sliceStride,
    int K, int cpz, int nc, int fold, char* sm)
{
    constexpr int n0 = (NV == 128) ? 0 : 128;
    constexpr int brows = (NV >= 128) ? 128 : ((NV + 15) & ~15);   // 128 or 80
    const int tid = threadIdx.x;
    const int lane = tid & 31;
    const int wid = tid >> 5;
    const int wm0 = (wid & 3) * 32;
    const int wn0 = (wid >> 2) * 64;
    const int m0 = blockIdx.x * 128;
    const int cpk = K / 64;
    const int lda = 2 * K;
    const int c0 = blockIdx.z * cpz;
    int c1 = c0 + cpz; if (c1 > nc) c1 = nc;

    const uint32_t sb = smem_u32(sm);
    float* Pz = P + (size_t)blockIdx.z * sliceStride;

    float acc[2][8][4];
    #pragma unroll
    for (int i = 0; i < 2; i++)
        #pragma unroll
        for (int j = 0; j < 8; j++)
            #pragma unroll
            for (int l = 0; l < 4; l++) acc[i][j][l] = 0.f;

    auto gissue = [&](int c, int st) {
        int region = c / cpk;
        int within = c - region * cpk;
        int acol = (region == 1 ? K : 0) + within * 64;
        int bcol = (region == 2 ? K : 0) + within * 64;
        uint32_t abase = sb + st * 32768;
        uint32_t bbase = abase + 16384;
        #pragma unroll
        for (int i = 0; i < 4; i++) {
            int idx = tid + 256 * i;
            int row = idx >> 3, q = idx & 7;
            cp16(abase + (row * 8 + (q ^ (row & 7))) * 16,
                 A + (size_t)(m0 + row) * lda + acol + q * 8);
        }
        #pragma unroll
        for (int i = 0; i < 4; i++) {
            int idx = tid + 256 * i;
            int row = idx >> 3, q = idx & 7;
            if (row < brows)     // compile-time bound
                cp16(bbase + (row * 8 + (q ^ (row & 7))) * 16,
                     B + (size_t)(n0 + row) * lda + bcol + q * 8);
        }
        cp_commit();
    };

    if (c0 < c1) gissue(c0, 0); else cp_commit();
    if (c0 + 1 < c1) gissue(c0 + 1, 1); else cp_commit();

    const int t3 = lane >> 3;
    const int r8 = lane & 7;
    const bool fullwarp = (NV >= 128) || (wn0 == 0);

    for (int c = c0; c < c1; c++) {
        int rel = c - c0;
        int st = rel % 3;
        cp_wait1();
        __syncthreads();
        if (c + 2 < c1) gissue(c + 2, (rel + 2) % 3);
        uint32_t ab = sb + st * 32768;
        uint32_t bb = ab + 16384;
        if (fullwarp) {
            // frag-pipelined: prefetch ks+1 LDSMs under the MMAs of ks
            uint32_t afr[2][2][4], bfr[2][4][4];
            auto ldfrags = [&](int buf, int ks) {
                int kc = ks * 2;
                #pragma unroll
                for (int mt = 0; mt < 2; mt++) {
                    int m = wm0 + mt * 16 + (t3 & 1) * 8 + r8;
                    int q = kc + (t3 >> 1);
                    ldm_x4(afr[buf][mt], ab + (m * 8 + (q ^ (m & 7))) * 16);
                }
                #pragma unroll
                for (int np = 0; np < 4; np++) {
                    int n = wn0 + np * 16 + (t3 >> 1) * 8 + r8;
                    int q = kc + (t3 & 1);
                    ldm_x4(bfr[np == 0 ? buf : buf][np], bb + (n * 8 + (q ^ (n & 7))) * 16);
                }
            };
            // load first ks into buffer 0
            {
                int kc = 0;
                #pragma unroll
                for (int mt = 0; mt < 2; mt++) {
                    int m = wm0 + mt * 16 + (t3 & 1) * 8 + r8;
                    int q = kc + (t3 >> 1);
                    ldm_x4(afr[0][mt], ab + (m * 8 + (q ^ (m & 7))) * 16);
                }
                #pragma unroll
                for (int np = 0; np < 4; np++) {
                    int n = wn0 + np * 16 + (t3 >> 1) * 8 + r8;
                    int q = kc + (t3 & 1);
                    ldm_x4(bfr[0][np], bb + (n * 8 + (q ^ (n & 7))) * 16);
                }
            }
            #pragma unroll
            for (int ks = 0; ks < 4; ks++) {
                int cur = ks & 1, nxt = cur ^ 1;
                if (ks < 3) {
                    int kc = (ks + 1) * 2;
                    #pragma unroll
                    for (int mt = 0; mt < 2; mt++) {
                        int m = wm0 + mt * 16 + (t3 & 1) * 8 + r8;
                        int q = kc + (t3 >> 1);
                        ldm_x4(afr[nxt][mt], ab + (m * 8 + (q ^ (m & 7))) * 16);
                    }
                    #pragma unroll
                    for (int np = 0; np < 4; np++) {
                        int n = wn0 + np * 16 + (t3 >> 1) * 8 + r8;
                        int q = kc + (t3 & 1);
                        ldm_x4(bfr[nxt][np], bb + (n * 8 + (q ^ (n & 7))) * 16);
                    }
                }
                #pragma unroll
                for (int mt = 0; mt < 2; mt++)
                    #pragma unroll
                    for (int nt = 0; nt < 8; nt++)
                        mma_bf16(acc[mt][nt], afr[cur][mt],
                                 bfr[cur][nt >> 1][(nt & 1) * 2],
                                 bfr[cur][nt >> 1][(nt & 1) * 2 + 1]);
            }
        } else {
            #pragma unroll
            for (int ks = 0; ks < 4; ks++) {
                int kc = ks * 2;
                uint32_t afr[2][4], bfr[4];
                #pragma unroll
                for (int mt = 0; mt < 2; mt++) {
                    int m = wm0 + mt * 16 + (t3 & 1) * 8 + r8;
                    int q = kc + (t3 >> 1);
                    ldm_x4(afr[mt], ab + (m * 8 + (q ^ (m & 7))) * 16);
                }
                int n = wn0 + (t3 >> 1) * 8 + r8;
                int q = kc + (t3 & 1);
                ldm_x4(bfr, bb + (n * 8 + (q ^ (n & 7))) * 16);
                #pragma unroll
                for (int mt = 0; mt < 2; mt++)
                    mma_bf16(acc[mt][0], afr[mt], bfr[0], bfr[1]);
            }
        }
    }

    // epilogue: plain vectorized stores into this z-slice
    const int g = lane >> 2, t = lane & 3;
    if (!fold) {
        #pragma unroll
        for (int mt = 0; mt < 2; mt++) {
            #pragma unroll
            for (int nt = 0; nt < 8; nt++) {
                int row = m0 + wm0 + mt * 16 + g;
                int col = n0 + wn0 + nt * 8 + t * 2;
                if (col < NJ) {
                    *reinterpret_cast<float2*>(&Pz[(size_t)row * NJ + col]) =
                        make_float2(acc[mt][nt][0], acc[mt][nt][1]);
                    *reinterpret_cast<float2*>(&Pz[(size_t)(row + 8) * NJ + col]) =
                        make_float2(acc[mt][nt][2], acc[mt][nt][3]);
                }
            }
        }
    } else {
        #pragma unroll
        for (int mt = 0; mt < 2; mt++) {
            #pragma unroll
            for (int nt = 0; nt < 8; nt++) {
                float v0 = acc[mt][nt][0] + __shfl_xor_sync(0xFFFFFFFFu, acc[mt][nt][0], 4);
                float v1 = acc[mt][nt][1] + __shfl_xor_sync(0xFFFFFFFFu, acc[mt][nt][1], 4);
                float v2 = acc[mt][nt][2] + __shfl_xor_sync(0xFFFFFFFFu, acc[mt][nt][2], 4);
                float v3 = acc[mt][nt][3] + __shfl_xor_sync(0xFFFFFFFFu, acc[mt][nt][3], 4);
                int row = m0 + wm0 + mt * 16 + g;
                int col = n0 + wn0 + nt * 8 + t * 2;
                if ((g & 1) == 0 && col < NJ) {
                    int or0 = row >> 1;
                    int or1 = (row + 8) >> 1;
                    *reinterpret_cast<float2*>(&Pz[(size_t)or0 * NJ + col]) = make_float2(v0, v1);
                    *reinterpret_cast<float2*>(&Pz[(size_t)or1 * NJ + col]) = make_float2(v2, v3);
                }
            }
        }
    }
}

__global__ void __launch_bounds__(256, 2) mma_gemm_kernel(
    const __nv_bfloat16* __restrict__ A,
    const __nv_bfloat16* __restrict__ B,
    float* __restrict__ P, size_t sliceStride,
    int K, int cpz, int nc, int fold)
{
    extern __shared__ char sm[];       // 3 stages x (A 16KB + B 16KB) = 96KB
    if (blockIdx.y == 0)
        gemm_body<128>(A, B, P, sliceStride, K, cpz, nc, fold, sm);
    else
        gemm_body<72>(A, B, P, sliceStride, K, cpz, nc, fold, sm);
}

// ---------------- sum Z0 partial slices -> O0 (2 float4 groups / thread) ------
__global__ void sum4_kernel(const float* __restrict__ P, float* __restrict__ O, int n4) {
    int i = blockIdx.x * 512 + threadIdx.x;
    const float4* p = reinterpret_cast<const float4*>(P);
    float4 r[2];
    #pragma unroll
    for (int j = 0; j < 2; j++) {
        int ii = i + j * 256;
        if (ii < n4) {
            float4 a = p[ii];
            float4 b = p[ii + n4];
            float4 c = p[ii + 2 * n4];
            float4 d = p[ii + 3 * n4];
            r[j] = make_float4(a.x + b.x + c.x + d.x, a.y + b.y + c.y + d.y,
                               a.z + b.z + c.z + d.z, a.w + b.w + c.w + d.w);
        }
    }
    #pragma unroll
    for (int j = 0; j < 2; j++) {
        int ii = i + j * 256;
        if (ii < n4) reinterpret_cast<float4*>(O)[ii] = r[j];
    }
}

// ---------------- Final reduce: [B, 400] ----------------
__global__ void reduce_kernel(const float* __restrict__ out0,
                              const float* __restrict__ P1,
                              float* __restrict__ res)
{
    int i = blockIdx.x * 256 + threadIdx.x;
    if (i >= BATCH * 2 * NJ) return;
    int b = i / (2 * NJ), j = i % (2 * NJ);
    if (j < NJ) {
        float s = 0.f;
        #pragma unroll
        for (int k = 0; k < KDIM; k++)
            s += out0[(size_t)(b * KDIM + k) * NJ + j];
        res[i] = s;
    } else {
        float s = 0.f;
        #pragma unroll
        for (int z = 0; z < Z1; z++)
            s += P1[(size_t)z * BATCH * NJ + (size_t)b * NJ + (j - NJ)];
        res[i] = s;
    }
}

extern "C" void kernel_launch(void* const* d_in, const int* in_sizes, int n_in,
                              void* d_out, int out_size)
{
    const float* inp = (const float*)d_in[0];
    const float* wq0 = (const float*)d_in[1];
    const float* wk0 = (const float*)d_in[2];
    const float* wv0 = (const float*)d_in[3];
    const float* cw0 = (const float*)d_in[4];
    const float* wq1 = (const float*)d_in[5];
    const float* wk1 = (const float*)d_in[6];
    const float* wv1 = (const float*)d_in[7];
    const float* cw1 = (const float*)d_in[8];
    float* out = (float*)d_out;

    __nv_bfloat16 *A0, *Xp, *B0, *B1;
    float *P0, *P1, *O0;
    cudaGetSymbolAddress((void**)&A0, g_A0);
    cudaGetSymbolAddress((void**)&Xp, g_Xp);
    cudaGetSymbolAddress((void**)&B0, g_B0);
    cudaGetSymbolAddress((void**)&B1, g_B1);
    cudaGetSymbolAddress((void**)&P0, g_P0);
    cudaGetSymbolAddress((void**)&P1, g_P1);
    cudaGetSymbolAddress((void**)&O0, g_O0);

    cudaFuncSetAttribute(mma_gemm_kernel, cudaFuncAttributeMaxDynamicSharedMemorySize, 98304);

    // both weight transposes + bf16 splits in ONE launch
    bprep2_kernel<<<dim3(C0 / 64 + C1 / 64, 8), 256>>>(cw0, cw1, B0, B1);

    // layer 0
    prep0_kernel<<<BATCH, 256>>>(inp, wq0, wk0, wv0, A0);
    // M=8192 (64 tiles), 2 n-tiles (compile-time specialized), nc=75, Z0=4 (cpz=19)
    mma_gemm_kernel<<<dim3(64, 2, Z0), 256, 98304>>>(A0, B0, P0, (size_t)M0 * NJ, C0, 19, 75, 0);
    sum4_kernel<<<(M0 * NJ / 4 + 511) / 512, 256>>>(P0, O0, M0 * NJ / 4);

    // layer 1 (k-presummed, column-owned producer)
    prep1_kernel<<<M1, 256>>>(inp, O0, wq1, wk1, wv1, Xp);
    // M=512 (4 tiles), nc=375 chunks, Z1=37 (cpz=11) -> 296 CTAs (1 full wave @ 2/SM)
    mma_gemm_kernel<<<dim3(4, 2, Z1), 256, 98304>>>(Xp, B1, P1, (size_t)BATCH * NJ, C1, 11, 375, 1);

    reduce_kernel<<<(BATCH * 2 * NJ + 255) / 256, 256>>>(O0, P1, out);
}

// round 12
// speedup vs baseline: 2.0362x; 1.1787x over previous
#include <cuda_runtime.h>
#include <cuda_fp16.h>
#include <cstdint>
#include <cstddef>

#define BATCH 256
#define F0    40
#define KDIM  32
#define NJ    200
#define C0    1600
#define C1    8000
#define M0    8192
#define KG    16
#define M1    512
#define Z0    4      // split-K slices layer 0
#define Z1    37     // split-K slices layer 1

// ---- scratch (static __device__, per harness rules) ----
__device__ __align__(16) __half g_A0[(size_t)M0 * 2 * C0];   // [8192, 3200]  hi|lo
__device__ __align__(16) __half g_Xp[(size_t)M1 * 2 * C1];   // [512, 16000]  hi|lo
__device__ __align__(16) __half g_B0[(size_t)256 * 2 * C0];  // [256, 3200]   hi|lo
__device__ __align__(16) __half g_B1[(size_t)256 * 2 * C1];  // [256, 16000]
__device__ __align__(16) float g_P0[(size_t)Z0 * M0 * NJ];   // gemm0 partials
__device__ __align__(16) float g_P1[(size_t)Z1 * BATCH * NJ];// gemm1 partials
__device__ __align__(16) float g_O0[(size_t)M0 * NJ];        // summed out0

// ================= helpers =================
__device__ __forceinline__ uint32_t smem_u32(const void* p) {
    uint32_t a;
    asm("{ .reg .u64 t; cvta.to.shared.u64 t, %1; cvt.u32.u64 %0, t; }" : "=r"(a) : "l"(p));
    return a;
}

__device__ __forceinline__ float ex2(float x) {
    float y;
    asm("ex2.approx.ftz.f32 %0, %1;" : "=f"(y) : "f"(x));
    return y;
}

__device__ __forceinline__ void ldm_x4(uint32_t* r, uint32_t addr) {
    asm volatile("ldmatrix.sync.aligned.m8n8.x4.shared.b16 {%0,%1,%2,%3}, [%4];"
        : "=r"(r[0]), "=r"(r[1]), "=r"(r[2]), "=r"(r[3]) : "r"(addr));
}

__device__ __forceinline__ void mma_f16(float* d, const uint32_t* a, uint32_t b0, uint32_t b1) {
    asm volatile("mma.sync.aligned.m16n8k16.row.col.f32.f16.f16.f32 "
        "{%0,%1,%2,%3}, {%4,%5,%6,%7}, {%8,%9}, {%0,%1,%2,%3};"
        : "+f"(d[0]), "+f"(d[1]), "+f"(d[2]), "+f"(d[3])
        : "r"(a[0]), "r"(a[1]), "r"(a[2]), "r"(a[3]), "r"(b0), "r"(b1));
}

__device__ __forceinline__ void cp16(uint32_t saddr, const void* gaddr) {
    asm volatile("cp.async.cg.shared.global [%0], [%1], 16;" :: "r"(saddr), "l"(gaddr));
}
__device__ __forceinline__ void cp_commit() { asm volatile("cp.async.commit_group;" ::: "memory"); }
__device__ __forceinline__ void cp_wait1()  { asm volatile("cp.async.wait_group 1;" ::: "memory"); }

__device__ __forceinline__ void split_store(__half* hi_p, __half* lo_p, float v) {
    __half h = __float2half(v);
    *hi_p = h;
    *lo_p = __float2half(v - __half2float(h));
}

// ================= weight prep (both weights, one launch, coalesced) ==========
__global__ void __launch_bounds__(256) bprep2_kernel(
    const float* __restrict__ cw0, const float* __restrict__ cw1,
    __half* __restrict__ B0w, __half* __restrict__ B1w)
{
    __shared__ float t[64][33];
    const int bx = blockIdx.x;
    const float* cw; __half* Bt; int C, cb;
    if (bx < C0 / 64) { cw = cw0; Bt = B0w; C = C0; cb = bx * 64; }
    else              { cw = cw1; Bt = B1w; C = C1; cb = (bx - C0 / 64) * 64; }
    const int jb = blockIdx.y * 32;

    int tx = threadIdx.x & 31, ty = threadIdx.x >> 5;   // j, c-sub
    #pragma unroll
    for (int r = 0; r < 64; r += 8) {
        int c = cb + ty + r;
        int j = jb + tx;
        t[ty + r][tx] = (j < NJ) ? cw[(size_t)c * NJ + j] : 0.f;
    }
    __syncthreads();
    int cx = threadIdx.x & 63, jy = threadIdx.x >> 6;   // c, j-sub
    #pragma unroll
    for (int r = 0; r < 32; r += 4) {
        int j = jb + jy + r;
        float v = t[cx][jy + r];
        split_store(&Bt[(size_t)j * (2 * C) + cb + cx],
                    &Bt[(size_t)j * (2 * C) + C + cb + cx], v);
    }
}

// ---------------- Layer 0 producer: column-owned, single barrier ----------------
__global__ void __launch_bounds__(256) prep0_kernel(
    const float* __restrict__ inp, const float* __restrict__ wq,
    const float* __restrict__ wk, const float* __restrict__ wv,
    __half* __restrict__ A0)
{
    __shared__ float u2[KDIM][F0], w[KDIM][F0], v[KDIM][F0];
    const int b = blockIdx.x;
    const int tid = threadIdx.x;

    for (int i = tid; i < KDIM * F0; i += 256) {
        int f = i >> 5, k = i & 31;          // k minor: coalesced
        float x = inp[(size_t)(b * F0 + f) * KDIM + k];
        u2[k][f] = x * wk[f * KDIM + k] * 1.44269504088896f;
        w[k][f]  = x * wv[f * KDIM + k];
        v[k][f]  = x * wq[f * KDIM + k];
    }
    __syncthreads();

    #pragma unroll
    for (int i = 0; i < 5; i++) {
        int idx = tid + 256 * i;             // 0..1279
        int k = idx / 40;
        int g = idx - k * 40;
        float vg = v[k][g];
        float e[F0];
        float s0 = 0.f, s1 = 0.f, s2 = 0.f, s3 = 0.f;
        #pragma unroll
        for (int f = 0; f < F0; f += 4) {
            e[f + 0] = ex2(u2[k][f + 0] * vg);
            e[f + 1] = ex2(u2[k][f + 1] * vg);
            e[f + 2] = ex2(u2[k][f + 2] * vg);
            e[f + 3] = ex2(u2[k][f + 3] * vg);
            s0 += e[f + 0]; s1 += e[f + 1]; s2 += e[f + 2]; s3 += e[f + 3];
        }
        float sinv = 1.0f / ((s0 + s1) + (s2 + s3));
        __half* rowp = A0 + (size_t)(b * KDIM + k) * (2 * C0);
        #pragma unroll
        for (int f = 0; f < F0; f++) {
            float val = w[k][f] * e[f] * sinv;
            split_store(&rowp[f * 40 + g], &rowp[C0 + f * 40 + g], val);
        }
    }
}

// ---------------- Layer 1 producer: column-owned, prefetched, chain-split ----
__global__ void __launch_bounds__(256) prep1_kernel(
    const float* __restrict__ inp, const float* __restrict__ out0,
    const float* __restrict__ wq, const float* __restrict__ wk,
    const float* __restrict__ wv, __half* __restrict__ Xp)
{
    __shared__ float u2[KG][F0], w[KG][F0];   // u2 = u * log2(e)
    const int blk = blockIdx.x;       // 512 = b*2 + kg
    const int kg = blk & 1;
    const int b = blk >> 1;
    const int tid = threadIdx.x;

    for (int i = tid; i < KG * F0; i += 256) {
        int kk = i / F0, f = i - kk * F0;
        int k = kg * KG + kk;
        float x = inp[(size_t)(b * F0 + f) * KDIM + k];
        u2[kk][f] = x * wk[f * KDIM + k] * 1.44269504088896f;
        w[kk][f] = x * wv[f * KDIM + k];
    }
    __syncthreads();

    if (tid >= NJ) return;            // no further barriers: safe
    const int g = tid;

    float wqv[KG];
    {
        const float4* wp = reinterpret_cast<const float4*>(wq + g * KDIM + kg * KG);
        #pragma unroll
        for (int q = 0; q < KG / 4; q++) {
            float4 t = wp[q];
            wqv[q * 4 + 0] = t.x; wqv[q * 4 + 1] = t.y;
            wqv[q * 4 + 2] = t.z; wqv[q * 4 + 3] = t.w;
        }
    }
    float v[KG];
    #pragma unroll
    for (int kk = 0; kk < KG; kk++) {
        int k = kg * KG + kk;
        v[kk] = out0[(size_t)(b * KDIM + k) * NJ + g];
    }
    #pragma unroll
    for (int kk = 0; kk < KG; kk++) v[kk] *= wqv[kk];

    float acc[F0];
    #pragma unroll
    for (int f = 0; f < F0; f++) acc[f] = 0.f;

    for (int kk = 0; kk < KG; kk++) {
        float vk = v[kk];
        float e[F0];
        float s0 = 0.f, s1 = 0.f, s2 = 0.f, s3 = 0.f;
        #pragma unroll
        for (int f = 0; f < F0; f += 4) {
            e[f + 0] = ex2(u2[kk][f + 0] * vk);
            e[f + 1] = ex2(u2[kk][f + 1] * vk);
            e[f + 2] = ex2(u2[kk][f + 2] * vk);
            e[f + 3] = ex2(u2[kk][f + 3] * vk);
            s0 += e[f + 0]; s1 += e[f + 1]; s2 += e[f + 2]; s3 += e[f + 3];
        }
        float sinv = 1.0f / ((s0 + s1) + (s2 + s3));
        #pragma unroll
        for (int f = 0; f < F0; f++)
            acc[f] += w[kk][f] * e[f] * sinv;
    }

    __half* rowp = Xp + (size_t)blk * (2 * C1);
    #pragma unroll
    for (int f = 0; f < F0; f++) {
        int c = f * NJ + g;
        split_store(&rowp[c], &rowp[C1 + c], acc[f]);
    }
}

// ---------------- mma.sync fp16x2 GEMM body, compile-time NV specialization ----
// 2 K-regions: region 0 = (A_hi, B_hi), region 1 = (A_lo, B_hi). nc = 2*(K/64).
template<int NV>
__device__ __forceinline__ void gemm_body(
    const __half* __restrict__ A,
    const __half* __restrict__ B,
    float* __restrict__ P, size_t sliceStride,
    int K, int cpz, int nc, int fold, char* sm)
{
    constexpr int n0 = (NV == 128) ? 0 : 128;
    constexpr int brows = (NV >= 128) ? 128 : ((NV + 15) & ~15);   // 128 or 80
    const int tid = threadIdx.x;
    const int lane = tid & 31;
    const int wid = tid >> 5;
    const int wm0 = (wid & 3) * 32;
    const int wn0 = (wid >> 2) * 64;
    const int m0 = blockIdx.x * 128;
    const int cpk = K / 64;
    const int lda = 2 * K;
    const int c0 = blockIdx.z * cpz;
    int c1 = c0 + cpz; if (c1 > nc) c1 = nc;

    const uint32_t sb = smem_u32(sm);
    float* Pz = P + (size_t)blockIdx.z * sliceStride;

    float acc[2][8][4];
    #pragma unroll
    for (int i = 0; i < 2; i++)
        #pragma unroll
        for (int j = 0; j < 8; j++)
            #pragma unroll
            for (int l = 0; l < 4; l++) acc[i][j][l] = 0.f;

    auto gissue = [&](int c, int st) {
        int region = c / cpk;
        int within = c - region * cpk;
        int acol = (region == 1 ? K : 0) + within * 64;
        int bcol = within * 64;              // B always hi region
        uint32_t abase = sb + st * 32768;
        uint32_t bbase = abase + 16384;
        #pragma unroll
        for (int i = 0; i < 4; i++) {
            int idx = tid + 256 * i;
            int row = idx >> 3, q = idx & 7;
            cp16(abase + (row * 8 + (q ^ (row & 7))) * 16,
                 A + (size_t)(m0 + row) * lda + acol + q * 8);
        }
        #pragma unroll
        for (int i = 0; i < 4; i++) {
            int idx = tid + 256 * i;
            int row = idx >> 3, q = idx & 7;
            if (row < brows)     // compile-time bound
                cp16(bbase + (row * 8 + (q ^ (row & 7))) * 16,
                     B + (size_t)(n0 + row) * lda + bcol + q * 8);
        }
        cp_commit();
    };

    if (c0 < c1) gissue(c0, 0); else cp_commit();
    if (c0 + 1 < c1) gissue(c0 + 1, 1); else cp_commit();

    const int t3 = lane >> 3;
    const int r8 = lane & 7;
    const bool fullwarp = (NV >= 128) || (wn0 == 0);

    for (int c = c0; c < c1; c++) {
        int rel = c - c0;
        int st = rel % 3;
        cp_wait1();
        __syncthreads();
        if (c + 2 < c1) gissue(c + 2, (rel + 2) % 3);
        uint32_t ab = sb + st * 32768;
        uint32_t bb = ab + 16384;
        #pragma unroll
        for (int ks = 0; ks < 4; ks++) {
            int kc = ks * 2;
            uint32_t afr[2][4], bfr[4][4];
            #pragma unroll
            for (int mt = 0; mt < 2; mt++) {
                int m = wm0 + mt * 16 + (t3 & 1) * 8 + r8;
                int q = kc + (t3 >> 1);
                ldm_x4(afr[mt], ab + (m * 8 + (q ^ (m & 7))) * 16);
            }
            if (fullwarp) {
                #pragma unroll
                for (int np = 0; np < 4; np++) {
                    int n = wn0 + np * 16 + (t3 >> 1) * 8 + r8;
                    int q = kc + (t3 & 1);
                    ldm_x4(bfr[np], bb + (n * 8 + (q ^ (n & 7))) * 16);
                }
                #pragma unroll
                for (int mt = 0; mt < 2; mt++)
                    #pragma unroll
                    for (int nt = 0; nt < 8; nt++)
                        mma_f16(acc[mt][nt], afr[mt],
                                bfr[nt >> 1][(nt & 1) * 2], bfr[nt >> 1][(nt & 1) * 2 + 1]);
            } else {
                int n = wn0 + (t3 >> 1) * 8 + r8;
                int q = kc + (t3 & 1);
                ldm_x4(bfr[0], bb + (n * 8 + (q ^ (n & 7))) * 16);
                #pragma unroll
                for (int mt = 0; mt < 2; mt++)
                    mma_f16(acc[mt][0], afr[mt], bfr[0][0], bfr[0][1]);
            }
        }
    }

    // epilogue: plain vectorized stores into this z-slice
    const int g = lane >> 2, t = lane & 3;
    if (!fold) {
        #pragma unroll
        for (int mt = 0; mt < 2; mt++) {
            #pragma unroll
            for (int nt = 0; nt < 8; nt++) {
                int row = m0 + wm0 + mt * 16 + g;
                int col = n0 + wn0 + nt * 8 + t * 2;
                if (col < NJ) {
                    *reinterpret_cast<float2*>(&Pz[(size_t)row * NJ + col]) =
                        make_float2(acc[mt][nt][0], acc[mt][nt][1]);
                    *reinterpret_cast<float2*>(&Pz[(size_t)(row + 8) * NJ + col]) =
                        make_float2(acc[mt][nt][2], acc[mt][nt][3]);
                }
            }
        }
    } else {
        #pragma unroll
        for (int mt = 0; mt < 2; mt++) {
            #pragma unroll
            for (int nt = 0; nt < 8; nt++) {
                float v0 = acc[mt][nt][0] + __shfl_xor_sync(0xFFFFFFFFu, acc[mt][nt][0], 4);
                float v1 = acc[mt][nt][1] + __shfl_xor_sync(0xFFFFFFFFu, acc[mt][nt][1], 4);
                float v2 = acc[mt][nt][2] + __shfl_xor_sync(0xFFFFFFFFu, acc[mt][nt][2], 4);
                float v3 = acc[mt][nt][3] + __shfl_xor_sync(0xFFFFFFFFu, acc[mt][nt][3], 4);
                int row = m0 + wm0 + mt * 16 + g;
                int col = n0 + wn0 + nt * 8 + t * 2;
                if ((g & 1) == 0 && col < NJ) {
                    int or0 = row >> 1;
                    int or1 = (row + 8) >> 1;
                    *reinterpret_cast<float2*>(&Pz[(size_t)or0 * NJ + col]) = make_float2(v0, v1);
                    *reinterpret_cast<float2*>(&Pz[(size_t)or1 * NJ + col]) = make_float2(v2, v3);
                }
            }
        }
    }
}

__global__ void __launch_bounds__(256, 2) mma_gemm_kernel(
    const __half* __restrict__ A,
    const __half* __restrict__ B,
    float* __restrict__ P, size_t sliceStride,
    int K, int cpz, int nc, int fold)
{
    extern __shared__ char sm[];       // 3 stages x (A 16KB + B 16KB) = 96KB
    if (blockIdx.y == 0)
        gemm_body<128>(A, B, P, sliceStride, K, cpz, nc, fold, sm);
    else
        gemm_body<72>(A, B, P, sliceStride, K, cpz, nc, fold, sm);
}

// ---------------- sum Z0 partial slices -> O0 (2 float4 groups / thread) ------
__global__ void sum4_kernel(const float* __restrict__ P, float* __restrict__ O, int n4) {
    int i = blockIdx.x * 512 + threadIdx.x;
    const float4* p = reinterpret_cast<const float4*>(P);
    float4 r[2];
    #pragma unroll
    for (int j = 0; j < 2; j++) {
        int ii = i + j * 256;
        if (ii < n4) {
            float4 a = p[ii];
            float4 b = p[ii + n4];
            float4 c = p[ii + 2 * n4];
            float4 d = p[ii + 3 * n4];
            r[j] = make_float4(a.x + b.x + c.x + d.x, a.y + b.y + c.y + d.y,
                               a.z + b.z + c.z + d.z, a.w + b.w + c.w + d.w);
        }
    }
    #pragma unroll
    for (int j = 0; j < 2; j++) {
        int ii = i + j * 256;
        if (ii < n4) reinterpret_cast<float4*>(O)[ii] = r[j];
    }
}

// ---------------- Final reduce: [B, 400] ----------------
__global__ void reduce_kernel(const float* __restrict__ out0,
                              const float* __restrict__ P1,
                              float* __restrict__ res)
{
    int i = blockIdx.x * 256 + threadIdx.x;
    if (i >= BATCH * 2 * NJ) return;
    int b = i / (2 * NJ), j = i % (2 * NJ);
    if (j < NJ) {
        float s = 0.f;
        #pragma unroll
        for (int k = 0; k < KDIM; k++)
            s += out0[(size_t)(b * KDIM + k) * NJ + j];
        res[i] = s;
    } else {
        float s = 0.f;
        #pragma unroll
        for (int z = 0; z < Z1; z++)
            s += P1[(size_t)z * BATCH * NJ + (size_t)b * NJ + (j - NJ)];
        res[i] = s;
    }
}

extern "C" void kernel_launch(void* const* d_in, const int* in_sizes, int n_in,
                              void* d_out, int out_size)
{
    const float* inp = (const float*)d_in[0];
    const float* wq0 = (const float*)d_in[1];
    const float* wk0 = (const float*)d_in[2];
    const float* wv0 = (const float*)d_in[3];
    const float* cw0 = (const float*)d_in[4];
    const float* wq1 = (const float*)d_in[5];
    const float* wk1 = (const float*)d_in[6];
    const float* wv1 = (const float*)d_in[7];
    const float* cw1 = (const float*)d_in[8];
    float* out = (float*)d_out;

    __half *A0, *Xp, *B0, *B1;
    float *P0, *P1, *O0;
    cudaGetSymbolAddress((void**)&A0, g_A0);
    cudaGetSymbolAddress((void**)&Xp, g_Xp);
    cudaGetSymbolAddress((void**)&B0, g_B0);
    cudaGetSymbolAddress((void**)&B1, g_B1);
    cudaGetSymbolAddress((void**)&P0, g_P0);
    cudaGetSymbolAddress((void**)&P1, g_P1);
    cudaGetSymbolAddress((void**)&O0, g_O0);

    cudaFuncSetAttribute(mma_gemm_kernel, cudaFuncAttributeMaxDynamicSharedMemorySize, 98304);

    // both weight transposes + fp16 splits in ONE launch
    bprep2_kernel<<<dim3(C0 / 64 + C1 / 64, 8), 256>>>(cw0, cw1, B0, B1);

    // layer 0
    prep0_kernel<<<BATCH, 256>>>(inp, wq0, wk0, wv0, A0);
    // M=8192 (64 tiles), 2 n-tiles, nc=50 chunks (fp16x2), Z0=4 (cpz=13)
    mma_gemm_kernel<<<dim3(64, 2, Z0), 256, 98304>>>(A0, B0, P0, (size_t)M0 * NJ, C0, 13, 50, 0);
    sum4_kernel<<<(M0 * NJ / 4 + 511) / 512, 256>>>(P0, O0, M0 * NJ / 4);

    // layer 1 (k-presummed, column-owned producer)
    prep1_kernel<<<M1, 256>>>(inp, O0, wq1, wk1, wv1, Xp);
    // M=512 (4 tiles), nc=250 chunks (fp16x2), Z1=37 (cpz=7) -> 296 CTAs
    mma_gemm_kernel<<<dim3(4, 2, Z1), 256, 98304>>>(Xp, B1, P1, (size_t)BATCH * NJ, C1, 7, 250, 1);

    reduce_kernel<<<(BATCH * 2 * NJ + 255) / 256, 256>>>(O0, P1, out);
}

// round 13
// speedup vs baseline: 2.8509x; 1.4001x over previous
#include <cuda_runtime.h>
#include <cuda_fp16.h>
#include <cstdint>
#include <cstddef>

#define BATCH 256
#define F0    40
#define KDIM  32
#define NJ    200
#define C0    1600
#define C1    8000
#define M0    8192
#define KG    16
#define M1    512
#define Z0    2      // split-K slices layer 0
#define Z1    37     // split-K slices layer 1

// ---- scratch (static __device__, per harness rules) ----
__device__ __align__(16) __half g_A0[(size_t)M0 * C0];       // [8192, 1600] fp16
__device__ __align__(16) __half g_Xp[(size_t)M1 * C1];       // [512, 8000]  fp16
__device__ __align__(16) __half g_B0[(size_t)256 * C0];      // [256, 1600]
__device__ __align__(16) __half g_B1[(size_t)256 * C1];      // [256, 8000]
__device__ __align__(16) float g_P0[(size_t)Z0 * M0 * NJ];   // gemm0 partials
__device__ __align__(16) float g_P1[(size_t)Z1 * BATCH * NJ];// gemm1 partials
__device__ __align__(16) float g_O0[(size_t)M0 * NJ];        // summed out0

// ================= helpers =================
__device__ __forceinline__ uint32_t smem_u32(const void* p) {
    uint32_t a;
    asm("{ .reg .u64 t; cvta.to.shared.u64 t, %1; cvt.u32.u64 %0, t; }" : "=r"(a) : "l"(p));
    return a;
}

__device__ __forceinline__ float ex2(float x) {
    float y;
    asm("ex2.approx.ftz.f32 %0, %1;" : "=f"(y) : "f"(x));
    return y;
}

__device__ __forceinline__ void ldm_x4(uint32_t* r, uint32_t addr) {
    asm volatile("ldmatrix.sync.aligned.m8n8.x4.shared.b16 {%0,%1,%2,%3}, [%4];"
        : "=r"(r[0]), "=r"(r[1]), "=r"(r[2]), "=r"(r[3]) : "r"(addr));
}

__device__ __forceinline__ void mma_f16(float* d, const uint32_t* a, uint32_t b0, uint32_t b1) {
    asm volatile("mma.sync.aligned.m16n8k16.row.col.f32.f16.f16.f32 "
        "{%0,%1,%2,%3}, {%4,%5,%6,%7}, {%8,%9}, {%0,%1,%2,%3};"
        : "+f"(d[0]), "+f"(d[1]), "+f"(d[2]), "+f"(d[3])
        : "r"(a[0]), "r"(a[1]), "r"(a[2]), "r"(a[3]), "r"(b0), "r"(b1));
}

__device__ __forceinline__ void cp16(uint32_t saddr, const void* gaddr) {
    asm volatile("cp.async.cg.shared.global [%0], [%1], 16;" :: "r"(saddr), "l"(gaddr));
}
__device__ __forceinline__ void cp_commit() { asm volatile("cp.async.commit_group;" ::: "memory"); }
__device__ __forceinline__ void cp_wait1()  { asm volatile("cp.async.wait_group 1;" ::: "memory"); }

// ================= weight prep (both weights, one launch, coalesced) ==========
__global__ void __launch_bounds__(256) bprep2_kernel(
    const float* __restrict__ cw0, const float* __restrict__ cw1,
    __half* __restrict__ B0w, __half* __restrict__ B1w)
{
    __shared__ float t[64][33];
    const int bx = blockIdx.x;
    const float* cw; __half* Bt; int C, cb;
    if (bx < C0 / 64) { cw = cw0; Bt = B0w; C = C0; cb = bx * 64; }
    else              { cw = cw1; Bt = B1w; C = C1; cb = (bx - C0 / 64) * 64; }
    const int jb = blockIdx.y * 32;

    int tx = threadIdx.x & 31, ty = threadIdx.x >> 5;   // j, c-sub
    #pragma unroll
    for (int r = 0; r < 64; r += 8) {
        int c = cb + ty + r;
        int j = jb + tx;
        t[ty + r][tx] = (j < NJ) ? cw[(size_t)c * NJ + j] : 0.f;
    }
    __syncthreads();
    int cx = threadIdx.x & 63, jy = threadIdx.x >> 6;   // c, j-sub
    #pragma unroll
    for (int r = 0; r < 32; r += 4) {
        int j = jb + jy + r;
        Bt[(size_t)j * C + cb + cx] = __float2half(t[cx][jy + r]);
    }
}

// ---------------- Layer 0 producer: column-owned, single barrier ----------------
__global__ void __launch_bounds__(256) prep0_kernel(
    const float* __restrict__ inp, const float* __restrict__ wq,
    const float* __restrict__ wk, const float* __restrict__ wv,
    __half* __restrict__ A0)
{
    __shared__ float u2[KDIM][F0], w[KDIM][F0], v[KDIM][F0];
    const int b = blockIdx.x;
    const int tid = threadIdx.x;

    for (int i = tid; i < KDIM * F0; i += 256) {
        int f = i >> 5, k = i & 31;          // k minor: coalesced
        float x = inp[(size_t)(b * F0 + f) * KDIM + k];
        u2[k][f] = x * wk[f * KDIM + k] * 1.44269504088896f;
        w[k][f]  = x * wv[f * KDIM + k];
        v[k][f]  = x * wq[f * KDIM + k];
    }
    __syncthreads();

    #pragma unroll
    for (int i = 0; i < 5; i++) {
        int idx = tid + 256 * i;             // 0..1279
        int k = idx / 40;
        int g = idx - k * 40;
        float vg = v[k][g];
        float e[F0];
        float s0 = 0.f, s1 = 0.f, s2 = 0.f, s3 = 0.f;
        #pragma unroll
        for (int f = 0; f < F0; f += 4) {
            e[f + 0] = ex2(u2[k][f + 0] * vg);
            e[f + 1] = ex2(u2[k][f + 1] * vg);
            e[f + 2] = ex2(u2[k][f + 2] * vg);
            e[f + 3] = ex2(u2[k][f + 3] * vg);
            s0 += e[f + 0]; s1 += e[f + 1]; s2 += e[f + 2]; s3 += e[f + 3];
        }
        float sinv = 1.0f / ((s0 + s1) + (s2 + s3));
        __half* rowp = A0 + (size_t)(b * KDIM + k) * C0;
        #pragma unroll
        for (int f = 0; f < F0; f++) {
            rowp[f * 40 + g] = __float2half(w[k][f] * e[f] * sinv);
        }
    }
}

// ---------------- Layer 1 producer: column-owned, prefetched, chain-split ----
__global__ void __launch_bounds__(256) prep1_kernel(
    const float* __restrict__ inp, const float* __restrict__ out0,
    const float* __restrict__ wq, const float* __restrict__ wk,
    const float* __restrict__ wv, __half* __restrict__ Xp)
{
    __shared__ float u2[KG][F0], w[KG][F0];   // u2 = u * log2(e)
    const int blk = blockIdx.x;       // 512 = b*2 + kg
    const int kg = blk & 1;
    const int b = blk >> 1;
    const int tid = threadIdx.x;

    for (int i = tid; i < KG * F0; i += 256) {
        int kk = i / F0, f = i - kk * F0;
        int k = kg * KG + kk;
        float x = inp[(size_t)(b * F0 + f) * KDIM + k];
        u2[kk][f] = x * wk[f * KDIM + k] * 1.44269504088896f;
        w[kk][f] = x * wv[f * KDIM + k];
    }
    __syncthreads();

    if (tid >= NJ) return;            // no further barriers: safe
    const int g = tid;

    float wqv[KG];
    {
        const float4* wp = reinterpret_cast<const float4*>(wq + g * KDIM + kg * KG);
        #pragma unroll
        for (int q = 0; q < KG / 4; q++) {
            float4 t = wp[q];
            wqv[q * 4 + 0] = t.x; wqv[q * 4 + 1] = t.y;
            wqv[q * 4 + 2] = t.z; wqv[q * 4 + 3] = t.w;
        }
    }
    float v[KG];
    #pragma unroll
    for (int kk = 0; kk < KG; kk++) {
        int k = kg * KG + kk;
        v[kk] = out0[(size_t)(b * KDIM + k) * NJ + g];
    }
    #pragma unroll
    for (int kk = 0; kk < KG; kk++) v[kk] *= wqv[kk];

    float acc[F0];
    #pragma unroll
    for (int f = 0; f < F0; f++) acc[f] = 0.f;

    for (int kk = 0; kk < KG; kk++) {
        float vk = v[kk];
        float e[F0];
        float s0 = 0.f, s1 = 0.f, s2 = 0.f, s3 = 0.f;
        #pragma unroll
        for (int f = 0; f < F0; f += 4) {
            e[f + 0] = ex2(u2[kk][f + 0] * vk);
            e[f + 1] = ex2(u2[kk][f + 1] * vk);
            e[f + 2] = ex2(u2[kk][f + 2] * vk);
            e[f + 3] = ex2(u2[kk][f + 3] * vk);
            s0 += e[f + 0]; s1 += e[f + 1]; s2 += e[f + 2]; s3 += e[f + 3];
        }
        float sinv = 1.0f / ((s0 + s1) + (s2 + s3));
        #pragma unroll
        for (int f = 0; f < F0; f++)
            acc[f] += w[kk][f] * e[f] * sinv;
    }

    __half* rowp = Xp + (size_t)blk * C1;
    #pragma unroll
    for (int f = 0; f < F0; f++) {
        rowp[f * NJ + g] = __float2half(acc[f]);
    }
}

// ---------------- mma.sync fp16 GEMM body, compile-time NV specialization ----
// Plain fp16: nc = K/64 chunks, lda = K.
template<int NV>
__device__ __forceinline__ void gemm_body(
    const __half* __restrict__ A,
    const __half* __restrict__ B,
    float* __restrict__ P, size_t sliceStride,
    int K, int cpz, int nc, int fold, char* sm)
{
    constexpr int n0 = (NV == 128) ? 0 : 128;
    constexpr int brows = (NV >= 128) ? 128 : ((NV + 15) & ~15);   // 128 or 80
    const int tid = threadIdx.x;
    const int lane = tid & 31;
    const int wid = tid >> 5;
    const int wm0 = (wid & 3) * 32;
    const int wn0 = (wid >> 2) * 64;
    const int m0 = blockIdx.x * 128;
    const int lda = K;
    const int c0 = blockIdx.z * cpz;
    int c1 = c0 + cpz; if (c1 > nc) c1 = nc;

    const uint32_t sb = smem_u32(sm);
    float* Pz = P + (size_t)blockIdx.z * sliceStride;

    float acc[2][8][4];
    #pragma unroll
    for (int i = 0; i < 2; i++)
        #pragma unroll
        for (int j = 0; j < 8; j++)
            #pragma unroll
            for (int l = 0; l < 4; l++) acc[i][j][l] = 0.f;

    auto gissue = [&](int c, int st) {
        int col = c * 64;
        uint32_t abase = sb + st * 32768;
        uint32_t bbase = abase + 16384;
        #pragma unroll
        for (int i = 0; i < 4; i++) {
            int idx = tid + 256 * i;
            int row = idx >> 3, q = idx & 7;
            cp16(abase + (row * 8 + (q ^ (row & 7))) * 16,
                 A + (size_t)(m0 + row) * lda + col + q * 8);
        }
        #pragma unroll
        for (int i = 0; i < 4; i++) {
            int idx = tid + 256 * i;
            int row = idx >> 3, q = idx & 7;
            if (row < brows)     // compile-time bound
                cp16(bbase + (row * 8 + (q ^ (row & 7))) * 16,
                     B + (size_t)(n0 + row) * lda + col + q * 8);
        }
        cp_commit();
    };

    if (c0 < c1) gissue(c0, 0); else cp_commit();
    if (c0 + 1 < c1) gissue(c0 + 1, 1); else cp_commit();

    const int t3 = lane >> 3;
    const int r8 = lane & 7;
    const bool fullwarp = (NV >= 128) || (wn0 == 0);

    for (int c = c0; c < c1; c++) {
        int rel = c - c0;
        int st = rel % 3;
        cp_wait1();
        __syncthreads();
        if (c + 2 < c1) gissue(c + 2, (rel + 2) % 3);
        uint32_t ab = sb + st * 32768;
        uint32_t bb = ab + 16384;
        #pragma unroll
        for (int ks = 0; ks < 4; ks++) {
            int kc = ks * 2;
            uint32_t afr[2][4], bfr[4][4];
            #pragma unroll
            for (int mt = 0; mt < 2; mt++) {
                int m = wm0 + mt * 16 + (t3 & 1) * 8 + r8;
                int q = kc + (t3 >> 1);
                ldm_x4(afr[mt], ab + (m * 8 + (q ^ (m & 7))) * 16);
            }
            if (fullwarp) {
                #pragma unroll
                for (int np = 0; np < 4; np++) {
                    int n = wn0 + np * 16 + (t3 >> 1) * 8 + r8;
                    int q = kc + (t3 & 1);
                    ldm_x4(bfr[np], bb + (n * 8 + (q ^ (n & 7))) * 16);
                }
                #pragma unroll
                for (int mt = 0; mt < 2; mt++)
                    #pragma unroll
                    for (int nt = 0; nt < 8; nt++)
                        mma_f16(acc[mt][nt], afr[mt],
                                bfr[nt >> 1][(nt & 1) * 2], bfr[nt >> 1][(nt & 1) * 2 + 1]);
            } else {
                int n = wn0 + (t3 >> 1) * 8 + r8;
                int q = kc + (t3 & 1);
                ldm_x4(bfr[0], bb + (n * 8 + (q ^ (n & 7))) * 16);
                #pragma unroll
                for (int mt = 0; mt < 2; mt++)
                    mma_f16(acc[mt][0], afr[mt], bfr[0][0], bfr[0][1]);
            }
        }
    }

    // epilogue: plain vectorized stores into this z-slice
    const int g = lane >> 2, t = lane & 3;
    if (!fold) {
        #pragma unroll
        for (int mt = 0; mt < 2; mt++) {
            #pragma unroll
            for (int nt = 0; nt < 8; nt++) {
                int row = m0 + wm0 + mt * 16 + g;
                int col = n0 + wn0 + nt * 8 + t * 2;
                if (col < NJ) {
                    *reinterpret_cast<float2*>(&Pz[(size_t)row * NJ + col]) =
                        make_float2(acc[mt][nt][0], acc[mt][nt][1]);
                    *reinterpret_cast<float2*>(&Pz[(size_t)(row + 8) * NJ + col]) =
                        make_float2(acc[mt][nt][2], acc[mt][nt][3]);
                }
            }
        }
    } else {
        #pragma unroll
        for (int mt = 0; mt < 2; mt++) {
            #pragma unroll
            for (int nt = 0; nt < 8; nt++) {
                float v0 = acc[mt][nt][0] + __shfl_xor_sync(0xFFFFFFFFu, acc[mt][nt][0], 4);
                float v1 = acc[mt][nt][1] + __shfl_xor_sync(0xFFFFFFFFu, acc[mt][nt][1], 4);
                float v2 = acc[mt][nt][2] + __shfl_xor_sync(0xFFFFFFFFu, acc[mt][nt][2], 4);
                float v3 = acc[mt][nt][3] + __shfl_xor_sync(0xFFFFFFFFu, acc[mt][nt][3], 4);
                int row = m0 + wm0 + mt * 16 + g;
                int col = n0 + wn0 + nt * 8 + t * 2;
                if ((g & 1) == 0 && col < NJ) {
                    int or0 = row >> 1;
                    int or1 = (row + 8) >> 1;
                    *reinterpret_cast<float2*>(&Pz[(size_t)or0 * NJ + col]) = make_float2(v0, v1);
                    *reinterpret_cast<float2*>(&Pz[(size_t)or1 * NJ + col]) = make_float2(v2, v3);
                }
            }
        }
    }
}

__global__ void __launch_bounds__(256, 2) mma_gemm_kernel(
    const __half* __restrict__ A,
    const __half* __restrict__ B,
    float* __restrict__ P, size_t sliceStride,
    int K, int cpz, int nc, int fold)
{
    extern __shared__ char sm[];       // 3 stages x (A 16KB + B 16KB) = 96KB
    if (blockIdx.y == 0)
        gemm_body<128>(A, B, P, sliceStride, K, cpz, nc, fold, sm);
    else
        gemm_body<72>(A, B, P, sliceStride, K, cpz, nc, fold, sm);
}

// ---------------- sum Z0 partial slices -> O0 (2 float4 groups / thread) ------
__global__ void sum2_kernel(const float* __restrict__ P, float* __restrict__ O, int n4) {
    int i = blockIdx.x * 512 + threadIdx.x;
    const float4* p = reinterpret_cast<const float4*>(P);
    float4 r[2];
    #pragma unroll
    for (int j = 0; j < 2; j++) {
        int ii = i + j * 256;
        if (ii < n4) {
            float4 a = p[ii];
            float4 b = p[ii + n4];
            r[j] = make_float4(a.x + b.x, a.y + b.y, a.z + b.z, a.w + b.w);
        }
    }
    #pragma unroll
    for (int j = 0; j < 2; j++) {
        int ii = i + j * 256;
        if (ii < n4) reinterpret_cast<float4*>(O)[ii] = r[j];
    }
}

// ---------------- Final reduce: [B, 400] ----------------
__global__ void reduce_kernel(const float* __restrict__ out0,
                              const float* __restrict__ P1,
                              float* __restrict__ res)
{
    int i = blockIdx.x * 256 + threadIdx.x;
    if (i >= BATCH * 2 * NJ) return;
    int b = i / (2 * NJ), j = i % (2 * NJ);
    if (j < NJ) {
        float s = 0.f;
        #pragma unroll
        for (int k = 0; k < KDIM; k++)
            s += out0[(size_t)(b * KDIM + k) * NJ + j];
        res[i] = s;
    } else {
        float s = 0.f;
        #pragma unroll
        for (int z = 0; z < Z1; z++)
            s += P1[(size_t)z * BATCH * NJ + (size_t)b * NJ + (j - NJ)];
        res[i] = s;
    }
}

extern "C" void kernel_launch(void* const* d_in, const int* in_sizes, int n_in,
                              void* d_out, int out_size)
{
    const float* inp = (const float*)d_in[0];
    const float* wq0 = (const float*)d_in[1];
    const float* wk0 = (const float*)d_in[2];
    const float* wv0 = (const float*)d_in[3];
    const float* cw0 = (const float*)d_in[4];
    const float* wq1 = (const float*)d_in[5];
    const float* wk1 = (const float*)d_in[6];
    const float* wv1 = (const float*)d_in[7];
    const float* cw1 = (const float*)d_in[8];
    float* out = (float*)d_out;

    __half *A0, *Xp, *B0, *B1;
    float *P0, *P1, *O0;
    cudaGetSymbolAddress((void**)&A0, g_A0);
    cudaGetSymbolAddress((void**)&Xp, g_Xp);
    cudaGetSymbolAddress((void**)&B0, g_B0);
    cudaGetSymbolAddress((void**)&B1, g_B1);
    cudaGetSymbolAddress((void**)&P0, g_P0);
    cudaGetSymbolAddress((void**)&P1, g_P1);
    cudaGetSymbolAddress((void**)&O0, g_O0);

    cudaFuncSetAttribute(mma_gemm_kernel, cudaFuncAttributeMaxDynamicSharedMemorySize, 98304);

    // both weight transposes + fp16 casts in ONE launch
    bprep2_kernel<<<dim3(C0 / 64 + C1 / 64, 8), 256>>>(cw0, cw1, B0, B1);

    // layer 0
    prep0_kernel<<<BATCH, 256>>>(inp, wq0, wk0, wv0, A0);
    // M=8192 (64 tiles), 2 n-tiles, nc=25 chunks (fp16), Z0=2 (cpz=13) -> 256 CTAs, 1 wave
    mma_gemm_kernel<<<dim3(64, 2, Z0), 256, 98304>>>(A0, B0, P0, (size_t)M0 * NJ, C0, 13, 25, 0);
    sum2_kernel<<<(M0 * NJ / 4 + 511) / 512, 256>>>(P0, O0, M0 * NJ / 4);

    // layer 1 (k-presummed, column-owned producer)
    prep1_kernel<<<M1, 256>>>(inp, O0, wq1, wk1, wv1, Xp);
    // M=512 (4 tiles), nc=125 chunks (fp16), Z1=37 (cpz=4) -> 296 CTAs (1 full wave)
    mma_gemm_kernel<<<dim3(4, 2, Z1), 256, 98304>>>(Xp, B1, P1, (size_t)BATCH * NJ, C1, 4, 125, 1);

    reduce_kernel<<<(BATCH * 2 * NJ + 255) / 256, 256>>>(O0, P1, out);
}

// round 14
// speedup vs baseline: 2.9849x; 1.0470x over previous
#include <cuda_runtime.h>
#include <cuda_fp16.h>
#include <cstdint>
#include <cstddef>

#define BATCH 256
#define F0    40
#define KDIM  32
#define NJ    200
#define C0    1600
#define C1    8000
#define M0    8192
#define KG    16
#define M1    512
#define Z0    2      // split-K slices layer 0
#define Z1    32     // split-K slices layer 1

// ---- scratch (static __device__, per harness rules) ----
__device__ __align__(16) __half g_A0[(size_t)M0 * C0];       // [8192, 1600] fp16
__device__ __align__(16) __half g_Xp[(size_t)M1 * C1];       // [512, 8000]  fp16
__device__ __align__(16) __half g_B0[(size_t)256 * C0];      // [256, 1600]
__device__ __align__(16) __half g_B1[(size_t)256 * C1];      // [256, 8000]
__device__ __align__(16) float g_P0[(size_t)Z0 * M0 * NJ];   // gemm0 partials (2 slices)
__device__ __align__(16) float g_P1[(size_t)Z1 * BATCH * NJ];// gemm1 partials

// ================= helpers =================
__device__ __forceinline__ uint32_t smem_u32(const void* p) {
    uint32_t a;
    asm("{ .reg .u64 t; cvta.to.shared.u64 t, %1; cvt.u32.u64 %0, t; }" : "=r"(a) : "l"(p));
    return a;
}

__device__ __forceinline__ float ex2(float x) {
    float y;
    asm("ex2.approx.ftz.f32 %0, %1;" : "=f"(y) : "f"(x));
    return y;
}

__device__ __forceinline__ void ldm_x4(uint32_t* r, uint32_t addr) {
    asm volatile("ldmatrix.sync.aligned.m8n8.x4.shared.b16 {%0,%1,%2,%3}, [%4];"
        : "=r"(r[0]), "=r"(r[1]), "=r"(r[2]), "=r"(r[3]) : "r"(addr));
}

__device__ __forceinline__ void mma_f16(float* d, const uint32_t* a, uint32_t b0, uint32_t b1) {
    asm volatile("mma.sync.aligned.m16n8k16.row.col.f32.f16.f16.f32 "
        "{%0,%1,%2,%3}, {%4,%5,%6,%7}, {%8,%9}, {%0,%1,%2,%3};"
        : "+f"(d[0]), "+f"(d[1]), "+f"(d[2]), "+f"(d[3])
        : "r"(a[0]), "r"(a[1]), "r"(a[2]), "r"(a[3]), "r"(b0), "r"(b1));
}

__device__ __forceinline__ void cp16(uint32_t saddr, const void* gaddr) {
    asm volatile("cp.async.cg.shared.global [%0], [%1], 16;" :: "r"(saddr), "l"(gaddr));
}
__device__ __forceinline__ void cp_commit() { asm volatile("cp.async.commit_group;" ::: "memory"); }
__device__ __forceinline__ void cp_wait1()  { asm volatile("cp.async.wait_group 1;" ::: "memory"); }

// ================= weight prep (both weights, one launch, coalesced) ==========
__global__ void __launch_bounds__(256) bprep2_kernel(
    const float* __restrict__ cw0, const float* __restrict__ cw1,
    __half* __restrict__ B0w, __half* __restrict__ B1w)
{
    __shared__ float t[64][33];
    const int bx = blockIdx.x;
    const float* cw; __half* Bt; int C, cb;
    if (bx < C0 / 64) { cw = cw0; Bt = B0w; C = C0; cb = bx * 64; }
    else              { cw = cw1; Bt = B1w; C = C1; cb = (bx - C0 / 64) * 64; }
    const int jb = blockIdx.y * 32;

    int tx = threadIdx.x & 31, ty = threadIdx.x >> 5;   // j, c-sub
    #pragma unroll
    for (int r = 0; r < 64; r += 8) {
        int c = cb + ty + r;
        int j = jb + tx;
        t[ty + r][tx] = (j < NJ) ? cw[(size_t)c * NJ + j] : 0.f;
    }
    __syncthreads();
    int cx = threadIdx.x & 63, jy = threadIdx.x >> 6;   // c, j-sub
    #pragma unroll
    for (int r = 0; r < 32; r += 4) {
        int j = jb + jy + r;
        Bt[(size_t)j * C + cb + cx] = __float2half(t[cx][jy + r]);
    }
}

// ---------------- Layer 0 producer: column-owned, single barrier ----------------
__global__ void __launch_bounds__(256) prep0_kernel(
    const float* __restrict__ inp, const float* __restrict__ wq,
    const float* __restrict__ wk, const float* __restrict__ wv,
    __half* __restrict__ A0)
{
    __shared__ float u2[KDIM][F0], w[KDIM][F0], v[KDIM][F0];
    const int b = blockIdx.x;
    const int tid = threadIdx.x;

    for (int i = tid; i < KDIM * F0; i += 256) {
        int f = i >> 5, k = i & 31;          // k minor: coalesced
        float x = inp[(size_t)(b * F0 + f) * KDIM + k];
        u2[k][f] = x * wk[f * KDIM + k] * 1.44269504088896f;
        w[k][f]  = x * wv[f * KDIM + k];
        v[k][f]  = x * wq[f * KDIM + k];
    }
    __syncthreads();

    #pragma unroll
    for (int i = 0; i < 5; i++) {
        int idx = tid + 256 * i;             // 0..1279
        int k = idx / 40;
        int g = idx - k * 40;
        float vg = v[k][g];
        float e[F0];
        float s0 = 0.f, s1 = 0.f, s2 = 0.f, s3 = 0.f;
        #pragma unroll
        for (int f = 0; f < F0; f += 4) {
            e[f + 0] = ex2(u2[k][f + 0] * vg);
            e[f + 1] = ex2(u2[k][f + 1] * vg);
            e[f + 2] = ex2(u2[k][f + 2] * vg);
            e[f + 3] = ex2(u2[k][f + 3] * vg);
            s0 += e[f + 0]; s1 += e[f + 1]; s2 += e[f + 2]; s3 += e[f + 3];
        }
        float sinv = 1.0f / ((s0 + s1) + (s2 + s3));
        __half* rowp = A0 + (size_t)(b * KDIM + k) * C0;
        #pragma unroll
        for (int f = 0; f < F0; f++) {
            rowp[f * 40 + g] = __float2half(w[k][f] * e[f] * sinv);
        }
    }
}

// ---------------- Layer 1 producer: reads BOTH gemm0 partial slices inline ----
__global__ void __launch_bounds__(256) prep1_kernel(
    const float* __restrict__ inp, const float* __restrict__ P0,
    const float* __restrict__ wq, const float* __restrict__ wk,
    const float* __restrict__ wv, __half* __restrict__ Xp)
{
    __shared__ float u2[KG][F0], w[KG][F0];   // u2 = u * log2(e)
    const int blk = blockIdx.x;       // 512 = b*2 + kg
    const int kg = blk & 1;
    const int b = blk >> 1;
    const int tid = threadIdx.x;
    const float* P0b = P0 + (size_t)M0 * NJ;

    for (int i = tid; i < KG * F0; i += 256) {
        int kk = i / F0, f = i - kk * F0;
        int k = kg * KG + kk;
        float x = inp[(size_t)(b * F0 + f) * KDIM + k];
        u2[kk][f] = x * wk[f * KDIM + k] * 1.44269504088896f;
        w[kk][f] = x * wv[f * KDIM + k];
    }
    __syncthreads();

    if (tid >= NJ) return;            // no further barriers: safe
    const int g = tid;

    float wqv[KG];
    {
        const float4* wp = reinterpret_cast<const float4*>(wq + g * KDIM + kg * KG);
        #pragma unroll
        for (int q = 0; q < KG / 4; q++) {
            float4 t = wp[q];
            wqv[q * 4 + 0] = t.x; wqv[q * 4 + 1] = t.y;
            wqv[q * 4 + 2] = t.z; wqv[q * 4 + 3] = t.w;
        }
    }
    float va[KG], vb[KG];
    #pragma unroll
    for (int kk = 0; kk < KG; kk++) {
        size_t idx = (size_t)(b * KDIM + kg * KG + kk) * NJ + g;
        va[kk] = P0[idx];
        vb[kk] = P0b[idx];
    }
    float v[KG];
    #pragma unroll
    for (int kk = 0; kk < KG; kk++) v[kk] = (va[kk] + vb[kk]) * wqv[kk];

    float acc[F0];
    #pragma unroll
    for (int f = 0; f < F0; f++) acc[f] = 0.f;

    for (int kk = 0; kk < KG; kk++) {
        float vk = v[kk];
        float e[F0];
        float s0 = 0.f, s1 = 0.f, s2 = 0.f, s3 = 0.f;
        #pragma unroll
        for (int f = 0; f < F0; f += 4) {
            e[f + 0] = ex2(u2[kk][f + 0] * vk);
            e[f + 1] = ex2(u2[kk][f + 1] * vk);
            e[f + 2] = ex2(u2[kk][f + 2] * vk);
            e[f + 3] = ex2(u2[kk][f + 3] * vk);
            s0 += e[f + 0]; s1 += e[f + 1]; s2 += e[f + 2]; s3 += e[f + 3];
        }
        float sinv = 1.0f / ((s0 + s1) + (s2 + s3));
        #pragma unroll
        for (int f = 0; f < F0; f++)
            acc[f] += w[kk][f] * e[f] * sinv;
    }

    __half* rowp = Xp + (size_t)blk * C1;
    #pragma unroll
    for (int f = 0; f < F0; f++) {
        rowp[f * NJ + g] = __float2half(acc[f]);
    }
}

// ---------------- mma.sync fp16 GEMM body, compile-time NV specialization ----
template<int NV>
__device__ __forceinline__ void gemm_body(
    const __half* __restrict__ A,
    const __half* __restrict__ B,
    float* __restrict__ P, size_t sliceStride,
    int K, int cpz, int nc, int fold, char* sm)
{
    constexpr int n0 = (NV == 128) ? 0 : 128;
    constexpr int brows = (NV >= 128) ? 128 : ((NV + 15) & ~15);   // 128 or 80
    const int tid = threadIdx.x;
    const int lane = tid & 31;
    const int wid = tid >> 5;
    const int wm0 = (wid & 3) * 32;
    const int wn0 = (wid >> 2) * 64;
    const int m0 = blockIdx.x * 128;
    const int lda = K;
    const int c0 = blockIdx.z * cpz;
    int c1 = c0 + cpz; if (c1 > nc) c1 = nc;

    const uint32_t sb = smem_u32(sm);
    float* Pz = P + (size_t)blockIdx.z * sliceStride;

    float acc[2][8][4];
    #pragma unroll
    for (int i = 0; i < 2; i++)
        #pragma unroll
        for (int j = 0; j < 8; j++)
            #pragma unroll
            for (int l = 0; l < 4; l++) acc[i][j][l] = 0.f;

    auto gissue = [&](int c, int st) {
        int col = c * 64;
        uint32_t abase = sb + st * 32768;
        uint32_t bbase = abase + 16384;
        #pragma unroll
        for (int i = 0; i < 4; i++) {
            int idx = tid + 256 * i;
            int row = idx >> 3, q = idx & 7;
            cp16(abase + (row * 8 + (q ^ (row & 7))) * 16,
                 A + (size_t)(m0 + row) * lda + col + q * 8);
        }
        #pragma unroll
        for (int i = 0; i < 4; i++) {
            int idx = tid + 256 * i;
            int row = idx >> 3, q = idx & 7;
            if (row < brows)     // compile-time bound
                cp16(bbase + (row * 8 + (q ^ (row & 7))) * 16,
                     B + (size_t)(n0 + row) * lda + col + q * 8);
        }
        cp_commit();
    };

    if (c0 < c1) gissue(c0, 0); else cp_commit();
    if (c0 + 1 < c1) gissue(c0 + 1, 1); else cp_commit();

    const int t3 = lane >> 3;
    const int r8 = lane & 7;
    const bool fullwarp = (NV >= 128) || (wn0 == 0);

    for (int c = c0; c < c1; c++) {
        int rel = c - c0;
        int st = rel % 3;
        cp_wait1();
        __syncthreads();
        if (c + 2 < c1) gissue(c + 2, (rel + 2) % 3);
        uint32_t ab = sb + st * 32768;
        uint32_t bb = ab + 16384;
        #pragma unroll
        for (int ks = 0; ks < 4; ks++) {
            int kc = ks * 2;
            uint32_t afr[2][4], bfr[4][4];
            #pragma unroll
            for (int mt = 0; mt < 2; mt++) {
                int m = wm0 + mt * 16 + (t3 & 1) * 8 + r8;
                int q = kc + (t3 >> 1);
                ldm_x4(afr[mt], ab + (m * 8 + (q ^ (m & 7))) * 16);
            }
            if (fullwarp) {
                #pragma unroll
                for (int np = 0; np < 4; np++) {
                    int n = wn0 + np * 16 + (t3 >> 1) * 8 + r8;
                    int q = kc + (t3 & 1);
                    ldm_x4(bfr[np], bb + (n * 8 + (q ^ (n & 7))) * 16);
                }
                #pragma unroll
                for (int mt = 0; mt < 2; mt++)
                    #pragma unroll
                    for (int nt = 0; nt < 8; nt++)
                        mma_f16(acc[mt][nt], afr[mt],
                                bfr[nt >> 1][(nt & 1) * 2], bfr[nt >> 1][(nt & 1) * 2 + 1]);
            } else {
                int n = wn0 + (t3 >> 1) * 8 + r8;
                int q = kc + (t3 & 1);
                ldm_x4(bfr[0], bb + (n * 8 + (q ^ (n & 7))) * 16);
                #pragma unroll
                for (int mt = 0; mt < 2; mt++)
                    mma_f16(acc[mt][0], afr[mt], bfr[0][0], bfr[0][1]);
            }
        }
    }

    // epilogue: plain vectorized stores into this z-slice
    const int g = lane >> 2, t = lane & 3;
    if (!fold) {
        #pragma unroll
        for (int mt = 0; mt < 2; mt++) {
            #pragma unroll
            for (int nt = 0; nt < 8; nt++) {
                int row = m0 + wm0 + mt * 16 + g;
                int col = n0 + wn0 + nt * 8 + t * 2;
                if (col < NJ) {
                    *reinterpret_cast<float2*>(&Pz[(size_t)row * NJ + col]) =
                        make_float2(acc[mt][nt][0], acc[mt][nt][1]);
                    *reinterpret_cast<float2*>(&Pz[(size_t)(row + 8) * NJ + col]) =
                        make_float2(acc[mt][nt][2], acc[mt][nt][3]);
                }
            }
        }
    } else {
        #pragma unroll
        for (int mt = 0; mt < 2; mt++) {
            #pragma unroll
            for (int nt = 0; nt < 8; nt++) {
                float v0 = acc[mt][nt][0] + __shfl_xor_sync(0xFFFFFFFFu, acc[mt][nt][0], 4);
                float v1 = acc[mt][nt][1] + __shfl_xor_sync(0xFFFFFFFFu, acc[mt][nt][1], 4);
                float v2 = acc[mt][nt][2] + __shfl_xor_sync(0xFFFFFFFFu, acc[mt][nt][2], 4);
                float v3 = acc[mt][nt][3] + __shfl_xor_sync(0xFFFFFFFFu, acc[mt][nt][3], 4);
                int row = m0 + wm0 + mt * 16 + g;
                int col = n0 + wn0 + nt * 8 + t * 2;
                if ((g & 1) == 0 && col < NJ) {
                    int or0 = row >> 1;
                    int or1 = (row + 8) >> 1;
                    *reinterpret_cast<float2*>(&Pz[(size_t)or0 * NJ + col]) = make_float2(v0, v1);
                    *reinterpret_cast<float2*>(&Pz[(size_t)or1 * NJ + col]) = make_float2(v2, v3);
                }
            }
        }
    }
}

__global__ void __launch_bounds__(256, 2) mma_gemm_kernel(
    const __half* __restrict__ A,
    const __half* __restrict__ B,
    float* __restrict__ P, size_t sliceStride,
    int K, int cpz, int nc, int fold)
{
    extern __shared__ char sm[];       // 3 stages x (A 16KB + B 16KB) = 96KB
    if (blockIdx.y == 0)
        gemm_body<128>(A, B, P, sliceStride, K, cpz, nc, fold, sm);
    else
        gemm_body<72>(A, B, P, sliceStride, K, cpz, nc, fold, sm);
}

// ---------------- Final reduce: [B, 400], sums gemm0 slices inline ----------
__global__ void reduce_kernel(const float* __restrict__ P0,
                              const float* __restrict__ P1,
                              float* __restrict__ res)
{
    int i = blockIdx.x * 256 + threadIdx.x;
    if (i >= BATCH * 2 * NJ) return;
    int b = i / (2 * NJ), j = i % (2 * NJ);
    if (j < NJ) {
        const float* P0b = P0 + (size_t)M0 * NJ;
        float s = 0.f;
        #pragma unroll
        for (int k = 0; k < KDIM; k++) {
            size_t idx = (size_t)(b * KDIM + k) * NJ + j;
            s += P0[idx] + P0b[idx];
        }
        res[i] = s;
    } else {
        float s = 0.f;
        #pragma unroll
        for (int z = 0; z < Z1; z++)
            s += P1[(size_t)z * BATCH * NJ + (size_t)b * NJ + (j - NJ)];
        res[i] = s;
    }
}

extern "C" void kernel_launch(void* const* d_in, const int* in_sizes, int n_in,
                              void* d_out, int out_size)
{
    const float* inp = (const float*)d_in[0];
    const float* wq0 = (const float*)d_in[1];
    const float* wk0 = (const float*)d_in[2];
    const float* wv0 = (const float*)d_in[3];
    const float* cw0 = (const float*)d_in[4];
    const float* wq1 = (const float*)d_in[5];
    const float* wk1 = (const float*)d_in[6];
    const float* wv1 = (const float*)d_in[7];
    const float* cw1 = (const float*)d_in[8];
    float* out = (float*)d_out;

    __half *A0, *Xp, *B0, *B1;
    float *P0, *P1;
    cudaGetSymbolAddress((void**)&A0, g_A0);
    cudaGetSymbolAddress((void**)&Xp, g_Xp);
    cudaGetSymbolAddress((void**)&B0, g_B0);
    cudaGetSymbolAddress((void**)&B1, g_B1);
    cudaGetSymbolAddress((void**)&P0, g_P0);
    cudaGetSymbolAddress((void**)&P1, g_P1);

    cudaFuncSetAttribute(mma_gemm_kernel, cudaFuncAttributeMaxDynamicSharedMemorySize, 98304);

    // both weight transposes + fp16 casts in ONE launch
    bprep2_kernel<<<dim3(C0 / 64 + C1 / 64, 8), 256>>>(cw0, cw1, B0, B1);

    // layer 0
    prep0_kernel<<<BATCH, 256>>>(inp, wq0, wk0, wv0, A0);
    // M=8192 (64 tiles), 2 n-tiles, nc=25 chunks (fp16), Z0=2 (cpz=13) -> 256 CTAs, 1 wave
    mma_gemm_kernel<<<dim3(64, 2, Z0), 256, 98304>>>(A0, B0, P0, (size_t)M0 * NJ, C0, 13, 25, 0);

    // layer 1 (k-presummed, column-owned producer; sums P0 slices inline)
    prep1_kernel<<<M1, 256>>>(inp, P0, wq1, wk1, wv1, Xp);
    // M=512 (4 tiles), nc=125 chunks (fp16), Z1=32 (cpz=4) -> 256 CTAs (1 wave)
    mma_gemm_kernel<<<dim3(4, 2, Z1), 256, 98304>>>(Xp, B1, P1, (size_t)BATCH * NJ, C1, 4, 125, 1);

    reduce_kernel<<<(BATCH * 2 * NJ + 255) / 256, 256>>>(P0, P1, out);
}